// round 3
// baseline (speedup 1.0000x reference)
#include <cuda_runtime.h>
#include <math.h>

#define N_NODES 150000
#define N_EDGES 2400000
#define F_IN 128
#define HID 32

// Scratch (allocation-free rule: __device__ globals)
__device__ float g_dinv[N_NODES];
__device__ float g_tmp[(size_t)N_NODES * HID];
__device__ float g_acc[(size_t)N_NODES * HID];
__device__ float g_tmp3[N_NODES];
__device__ float g_acc3[N_NODES];

// ---------------- degree ----------------
__global__ void k_deg_init() {
    int i = blockIdx.x * blockDim.x + threadIdx.x;
    if (i < N_NODES) g_dinv[i] = 1.0f;  // self-loop contributes 1
}

__global__ void k_deg_count(const int* __restrict__ dst) {
    int e = blockIdx.x * blockDim.x + threadIdx.x;
    if (e < N_EDGES) atomicAdd(&g_dinv[dst[e]], 1.0f);
}

__global__ void k_deg_finish() {
    int i = blockIdx.x * blockDim.x + threadIdx.x;
    if (i < N_NODES) g_dinv[i] = rsqrtf(fmaxf(g_dinv[i], 1.0f));
}

// ---------------- layer 1 transform: tmp = dinv * (x @ W1); acc = tmp ----------------
__global__ void k_xform1(const float* __restrict__ x, const float* __restrict__ W1) {
    __shared__ float sW[F_IN * HID];   // 16 KB
    __shared__ float sx[8][F_IN];      // 4 KB
    int tid = threadIdx.x;             // 256 threads = 8 rows x 32 feats
    for (int i = tid; i < F_IN * HID; i += 256) sW[i] = W1[i];
    int row0 = blockIdx.x * 8;
    for (int i = tid; i < 8 * F_IN; i += 256) {
        int r = i / F_IN, c = i % F_IN;
        int row = row0 + r;
        sx[r][c] = (row < N_NODES) ? x[(size_t)row * F_IN + c] : 0.0f;
    }
    __syncthreads();
    int r = tid >> 5, f = tid & 31;
    int row = row0 + r;
    if (row < N_NODES) {
        float t = 0.0f;
#pragma unroll
        for (int k = 0; k < F_IN; k++) t = fmaf(sx[r][k], sW[k * HID + f], t);
        float v = g_dinv[row] * t;
        size_t o = (size_t)row * HID + f;
        g_tmp[o] = v;
        g_acc[o] = v;   // self-loop init
    }
}

// ---------------- 32-wide edge aggregation: acc[dst] += tmp[src] ----------------
__global__ void k_edge32(const int* __restrict__ src,
                         const int* __restrict__ dst) {
    int w = (blockIdx.x * blockDim.x + threadIdx.x) >> 5;
    int lane = threadIdx.x & 31;
    if (w < N_EDGES) {
        int s = __ldg(&src[w]);
        int d = __ldg(&dst[w]);
        float v = g_tmp[(size_t)s * HID + lane];
        atomicAdd(&g_acc[(size_t)d * HID + lane], v);
    }
}

// ---------------- layer 2 transform ----------------
__global__ void k_xform2(const float* __restrict__ W2, const float* __restrict__ b1) {
    __shared__ float sW[HID * HID];
    __shared__ float sy[8][HID];
    int tid = threadIdx.x;  // 256
    for (int i = tid; i < HID * HID; i += 256) sW[i] = W2[i];
    __syncthreads();
    int r = tid >> 5, f = tid & 31;
    int row = blockIdx.x * 8 + r;
    if (row >= N_NODES) return;  // warp-uniform exit (r uniform per warp)
    float di = g_dinv[row];
    size_t o = (size_t)row * HID + f;
    float y = fmaxf(fmaf(di, g_acc[o], b1[f]), 0.0f);
    sy[r][f] = y;
    __syncwarp();
    float t = 0.0f;
#pragma unroll
    for (int k = 0; k < HID; k++) t = fmaf(sy[r][k], sW[k * HID + f], t);
    float v = di * t;
    g_tmp[o] = v;
    g_acc[o] = v;
}

// ---------------- layer 3 transform ----------------
__global__ void k_xform3(const float* __restrict__ W3, const float* __restrict__ b2) {
    int tid = blockIdx.x * blockDim.x + threadIdx.x;
    int row = tid >> 5;
    int f = tid & 31;
    if (row >= N_NODES) return;
    float di = g_dinv[row];
    float y = fmaxf(fmaf(di, g_acc[(size_t)row * HID + f], b2[f]), 0.0f);
    float t = y * __ldg(&W3[f]);
#pragma unroll
    for (int o = 16; o > 0; o >>= 1) t += __shfl_down_sync(0xffffffffu, t, o);
    if (f == 0) {
        float v = di * t;
        g_tmp3[row] = v;
        g_acc3[row] = v;
    }
}

// ---------------- scalar edge aggregation ----------------
__global__ void k_edge1(const int* __restrict__ src,
                        const int* __restrict__ dst) {
    int e = blockIdx.x * blockDim.x + threadIdx.x;
    if (e < N_EDGES) {
        atomicAdd(&g_acc3[dst[e]], g_tmp3[src[e]]);
    }
}

// ---------------- final sigmoid ----------------
__global__ void k_final(const float* __restrict__ b3, float* __restrict__ out) {
    int i = blockIdx.x * blockDim.x + threadIdx.x;
    if (i < N_NODES) {
        float z = fmaf(g_dinv[i], g_acc3[i], b3[0]);
        out[i] = 1.0f / (1.0f + __expf(-z));
    }
}

extern "C" void kernel_launch(void* const* d_in, const int* in_sizes, int n_in,
                              void* d_out, int out_size) {
    // Resolve inputs by element count — robust to metadata ordering.
    // x: 19200000, edge_index: 4800000 (int32!), W1: 4096, W2: 1024, b3: 1
    // b1, b2, W3 all have 32 elements; disambiguate by overall ordering scheme.
    int ix = -1, ie = -1, iw1 = -1, iw2 = -1, ib3 = -1;
    int i32[3], n32 = 0;
    for (int i = 0; i < n_in; i++) {
        switch (in_sizes[i]) {
            case 19200000: ix = i; break;
            case 4800000:  ie = i; break;
            case 4096:     iw1 = i; break;
            case 1024:     iw2 = i; break;
            case 1:        ib3 = i; break;
            case 32:       if (n32 < 3) i32[n32++] = i; break;
            default: break;
        }
    }
    int ib1, ib2, iw3;
    if (ie == 1) {
        // dict order: x, edge_index, W1, b1, W2, b2, W3, b3 -> 32-sized are b1,b2,W3 ascending
        ib1 = i32[0]; ib2 = i32[1]; iw3 = i32[2];
    } else {
        // alphabetical: W1, W2, W3, b1, b2, b3, edge_index, x -> 32-sized are W3,b1,b2 ascending
        iw3 = i32[0]; ib1 = i32[1]; ib2 = i32[2];
    }

    const float* x  = (const float*)d_in[ix];
    const int* ei   = (const int*)d_in[ie];   // [2, E] int32 (JAX x64 disabled demotes int64)
    const float* W1 = (const float*)d_in[iw1];
    const float* b1 = (const float*)d_in[ib1];
    const float* W2 = (const float*)d_in[iw2];
    const float* b2 = (const float*)d_in[ib2];
    const float* W3 = (const float*)d_in[iw3];
    const float* b3 = (const float*)d_in[ib3];
    float* out = (float*)d_out;

    const int* src = ei;
    const int* dst = ei + N_EDGES;

    const int T = 256;
    int nblk_nodes = (N_NODES + T - 1) / T;
    int nblk_edges = (N_EDGES + T - 1) / T;
    int nblk_rows8 = (N_NODES + 7) / 8;                 // 8 rows per 256-thread block
    int nblk_edgewarp = (N_EDGES * 32 + T - 1) / T;     // 1 warp per edge
    int nblk_rowwarp = (N_NODES * 32 + T - 1) / T;      // 1 warp per row

    // degree / normalization
    k_deg_init<<<nblk_nodes, T>>>();
    k_deg_count<<<nblk_edges, T>>>(dst);
    k_deg_finish<<<nblk_nodes, T>>>();

    // layer 1
    k_xform1<<<nblk_rows8, T>>>(x, W1);
    k_edge32<<<nblk_edgewarp, T>>>(src, dst);

    // layer 2
    k_xform2<<<nblk_rows8, T>>>(W2, b1);
    k_edge32<<<nblk_edgewarp, T>>>(src, dst);

    // layer 3
    k_xform3<<<nblk_rowwarp, T>>>(W3, b2);
    k_edge1<<<nblk_edges, T>>>(src, dst);

    k_final<<<nblk_nodes, T>>>(b3, out);
}

// round 4
// speedup vs baseline: 2.3419x; 2.3419x over previous
#include <cuda_runtime.h>
#include <math.h>

#define N_NODES 150000
#define N_EDGES 2400000
#define F_IN 128
#define HID 32
#define SCAN_BS 256
#define SCAN_NB ((N_NODES + SCAN_BS - 1) / SCAN_BS)   // 586

// Scratch (allocation-free rule: __device__ globals)
__device__ float g_dinv[N_NODES];
__device__ float g_tmp[(size_t)N_NODES * HID];
__device__ float g_acc[(size_t)N_NODES * HID];
__device__ float g_tmp3[N_NODES];
__device__ int   g_cnt[N_NODES];
__device__ int   g_rowptr[N_NODES + 1];
__device__ int   g_cursor[N_NODES];
__device__ int   g_bsum[1024];
__device__ int   g_boff[1024];
__device__ int   g_csr_src[N_EDGES];

// ---------------- CSR build ----------------
__global__ void k_zero_cnt() {
    int i = blockIdx.x * blockDim.x + threadIdx.x;
    if (i < N_NODES) g_cnt[i] = 0;
}

__global__ void k_hist(const int* __restrict__ dst) {
    int e = blockIdx.x * blockDim.x + threadIdx.x;
    if (e < N_EDGES) atomicAdd(&g_cnt[dst[e]], 1);
}

__global__ void k_scan_a() {
    __shared__ int sh[SCAN_BS];
    int tid = threadIdx.x;
    int i = blockIdx.x * SCAN_BS + tid;
    int v = (i < N_NODES) ? g_cnt[i] : 0;
    sh[tid] = v;
    __syncthreads();
#pragma unroll
    for (int off = 1; off < SCAN_BS; off <<= 1) {
        int t = (tid >= off) ? sh[tid - off] : 0;
        __syncthreads();
        sh[tid] += t;
        __syncthreads();
    }
    int incl = sh[tid];
    if (i < N_NODES) g_rowptr[i] = incl - v;   // block-local exclusive
    if (tid == SCAN_BS - 1) g_bsum[blockIdx.x] = incl;
}

__global__ void k_scan_b() {
    __shared__ int sh[1024];
    int tid = threadIdx.x;
    int v = (tid < SCAN_NB) ? g_bsum[tid] : 0;
    sh[tid] = v;
    __syncthreads();
#pragma unroll
    for (int off = 1; off < 1024; off <<= 1) {
        int t = (tid >= off) ? sh[tid - off] : 0;
        __syncthreads();
        sh[tid] += t;
        __syncthreads();
    }
    if (tid < SCAN_NB) g_boff[tid] = sh[tid] - v;
}

__global__ void k_scan_c() {
    int i = blockIdx.x * blockDim.x + threadIdx.x;
    if (i < N_NODES) {
        int r = g_rowptr[i] + g_boff[i >> 8];
        g_rowptr[i] = r;
        g_cursor[i] = r;
        g_dinv[i] = rsqrtf((float)(g_cnt[i] + 1));  // +1 self loop, deg>=1
    }
    if (i == 0) g_rowptr[N_NODES] = N_EDGES;
}

__global__ void k_fill(const int* __restrict__ src, const int* __restrict__ dst) {
    int e = blockIdx.x * blockDim.x + threadIdx.x;
    if (e < N_EDGES) {
        int p = atomicAdd(&g_cursor[dst[e]], 1);
        g_csr_src[p] = src[e];
    }
}

// ---------------- layer 1 transform: tmp = dinv * (x @ W1) ----------------
// 256 thr = 8 warps; each warp: 4 rows x 32 feats; block = 32 rows.
__global__ void k_xform1(const float* __restrict__ x, const float* __restrict__ W1) {
    __shared__ __align__(16) float sW[F_IN * HID];   // 16 KB
    __shared__ __align__(16) float sx[32 * F_IN];    // 16 KB
    int tid = threadIdx.x;
    int row0 = blockIdx.x * 32;

    // load W1 (4096 floats) via float4
    {
        const float4* Wv = (const float4*)W1;
        float4* sWv = (float4*)sW;
        for (int i = tid; i < F_IN * HID / 4; i += 256) sWv[i] = Wv[i];
    }
    // load 32 rows of x (4096 contiguous floats) via float4, guarded for tail block
    if (row0 + 32 <= N_NODES) {
        const float4* xv = (const float4*)(x + (size_t)row0 * F_IN);
        float4* sxv = (float4*)sx;
        for (int i = tid; i < 32 * F_IN / 4; i += 256) sxv[i] = xv[i];
    } else {
        for (int i = tid; i < 32 * F_IN; i += 256) {
            int r = i / F_IN;
            sx[i] = (row0 + r < N_NODES) ? x[(size_t)(row0 + r) * F_IN + (i % F_IN)] : 0.0f;
        }
    }
    __syncthreads();

    int w = tid >> 5, f = tid & 31;
    float acc0 = 0.f, acc1 = 0.f, acc2 = 0.f, acc3 = 0.f;
    const float* sx0 = &sx[(w * 4 + 0) * F_IN];
    const float* sx1 = &sx[(w * 4 + 1) * F_IN];
    const float* sx2 = &sx[(w * 4 + 2) * F_IN];
    const float* sx3 = &sx[(w * 4 + 3) * F_IN];
#pragma unroll
    for (int k4 = 0; k4 < F_IN; k4 += 4) {
        float4 xa = *(const float4*)(sx0 + k4);
        float4 xb = *(const float4*)(sx1 + k4);
        float4 xc = *(const float4*)(sx2 + k4);
        float4 xd = *(const float4*)(sx3 + k4);
        float w0 = sW[(k4 + 0) * HID + f];
        float w1 = sW[(k4 + 1) * HID + f];
        float w2 = sW[(k4 + 2) * HID + f];
        float w3 = sW[(k4 + 3) * HID + f];
        acc0 = fmaf(xa.x, w0, fmaf(xa.y, w1, fmaf(xa.z, w2, fmaf(xa.w, w3, acc0))));
        acc1 = fmaf(xb.x, w0, fmaf(xb.y, w1, fmaf(xb.z, w2, fmaf(xb.w, w3, acc1))));
        acc2 = fmaf(xc.x, w0, fmaf(xc.y, w1, fmaf(xc.z, w2, fmaf(xc.w, w3, acc2))));
        acc3 = fmaf(xd.x, w0, fmaf(xd.y, w1, fmaf(xd.z, w2, fmaf(xd.w, w3, acc3))));
    }
    float a[4] = {acc0, acc1, acc2, acc3};
#pragma unroll
    for (int j = 0; j < 4; j++) {
        int row = row0 + w * 4 + j;
        if (row < N_NODES) g_tmp[(size_t)row * HID + f] = g_dinv[row] * a[j];
    }
}

// ---------------- CSR gather aggregation (32-wide): acc[n] = tmp[n] + sum tmp[src] ----------------
__global__ void k_agg32() {
    int n = blockIdx.x * 8 + (threadIdx.x >> 5);
    int lane = threadIdx.x & 31;
    if (n >= N_NODES) return;  // warp-uniform
    int s = g_rowptr[n];
    int sE = g_rowptr[n + 1];
    float a = g_tmp[(size_t)n * HID + lane];  // self loop
    int e = s;
    for (; e + 4 <= sE; e += 4) {
        int i0 = g_csr_src[e + 0];
        int i1 = g_csr_src[e + 1];
        int i2 = g_csr_src[e + 2];
        int i3 = g_csr_src[e + 3];
        float v0 = g_tmp[(size_t)i0 * HID + lane];
        float v1 = g_tmp[(size_t)i1 * HID + lane];
        float v2 = g_tmp[(size_t)i2 * HID + lane];
        float v3 = g_tmp[(size_t)i3 * HID + lane];
        a += (v0 + v1) + (v2 + v3);
    }
    for (; e < sE; e++) a += g_tmp[(size_t)g_csr_src[e] * HID + lane];
    g_acc[(size_t)n * HID + lane] = a;
}

// ---------------- layer 2 transform: y = relu(dinv*acc + b1); tmp = dinv*(y@W2) ----------------
__global__ void k_xform2(const float* __restrict__ W2, const float* __restrict__ b1) {
    __shared__ float sW[HID * HID];
    __shared__ float sy[8][HID];
    int tid = threadIdx.x;  // 256
    for (int i = tid; i < HID * HID; i += 256) sW[i] = W2[i];
    __syncthreads();
    int r = tid >> 5, f = tid & 31;
    int row = blockIdx.x * 8 + r;
    if (row >= N_NODES) return;  // warp-uniform
    float di = g_dinv[row];
    size_t o = (size_t)row * HID + f;
    float y = fmaxf(fmaf(di, g_acc[o], b1[f]), 0.0f);
    sy[r][f] = y;
    __syncwarp();
    float t = 0.0f;
#pragma unroll
    for (int k = 0; k < HID; k++) t = fmaf(sy[r][k], sW[k * HID + f], t);
    g_tmp[o] = di * t;
}

// ---------------- layer 3 transform: tmp3 = dinv*(relu(dinv*acc+b2) @ W3) ----------------
__global__ void k_xform3(const float* __restrict__ W3, const float* __restrict__ b2) {
    int tid = blockIdx.x * blockDim.x + threadIdx.x;
    int row = tid >> 5;
    int f = tid & 31;
    if (row >= N_NODES) return;
    float di = g_dinv[row];
    float y = fmaxf(fmaf(di, g_acc[(size_t)row * HID + f], b2[f]), 0.0f);
    float t = y * __ldg(&W3[f]);
#pragma unroll
    for (int o = 16; o > 0; o >>= 1) t += __shfl_down_sync(0xffffffffu, t, o);
    if (f == 0) g_tmp3[row] = di * t;
}

// ---------------- scalar gather + final sigmoid ----------------
__global__ void k_agg1_final(const float* __restrict__ b3, float* __restrict__ out) {
    int n = blockIdx.x * blockDim.x + threadIdx.x;
    if (n >= N_NODES) return;
    int s = g_rowptr[n];
    int sE = g_rowptr[n + 1];
    float a = g_tmp3[n];  // self loop
    int e = s;
    for (; e + 4 <= sE; e += 4) {
        float v0 = g_tmp3[g_csr_src[e + 0]];
        float v1 = g_tmp3[g_csr_src[e + 1]];
        float v2 = g_tmp3[g_csr_src[e + 2]];
        float v3 = g_tmp3[g_csr_src[e + 3]];
        a += (v0 + v1) + (v2 + v3);
    }
    for (; e < sE; e++) a += g_tmp3[g_csr_src[e]];
    float z = fmaf(g_dinv[n], a, b3[0]);
    out[n] = 1.0f / (1.0f + __expf(-z));
}

extern "C" void kernel_launch(void* const* d_in, const int* in_sizes, int n_in,
                              void* d_out, int out_size) {
    // Resolve inputs by element count — robust to metadata ordering.
    int ix = -1, ie = -1, iw1 = -1, iw2 = -1, ib3 = -1;
    int i32[3], n32 = 0;
    for (int i = 0; i < n_in; i++) {
        switch (in_sizes[i]) {
            case 19200000: ix = i; break;
            case 4800000:  ie = i; break;
            case 4096:     iw1 = i; break;
            case 1024:     iw2 = i; break;
            case 1:        ib3 = i; break;
            case 32:       if (n32 < 3) i32[n32++] = i; break;
            default: break;
        }
    }
    int ib1, ib2, iw3;
    if (ie == 1) {  // dict order: x, edge_index, W1, b1, W2, b2, W3, b3
        ib1 = i32[0]; ib2 = i32[1]; iw3 = i32[2];
    } else {        // alphabetical: W1, W2, W3, b1, b2, b3, edge_index, x
        iw3 = i32[0]; ib1 = i32[1]; ib2 = i32[2];
    }

    const float* x  = (const float*)d_in[ix];
    const int* ei   = (const int*)d_in[ie];   // [2, E] int32
    const float* W1 = (const float*)d_in[iw1];
    const float* b1 = (const float*)d_in[ib1];
    const float* W2 = (const float*)d_in[iw2];
    const float* b2 = (const float*)d_in[ib2];
    const float* W3 = (const float*)d_in[iw3];
    const float* b3 = (const float*)d_in[ib3];
    float* out = (float*)d_out;

    const int* src = ei;
    const int* dst = ei + N_EDGES;

    const int T = 256;
    int nblk_nodes = (N_NODES + T - 1) / T;
    int nblk_edges = (N_EDGES + T - 1) / T;
    int nblk_x1 = (N_NODES + 31) / 32;
    int nblk_rows8 = (N_NODES + 7) / 8;
    int nblk_rowwarp = ((size_t)N_NODES * 32 + T - 1) / T;

    // CSR build (+ degree normalization as byproduct)
    k_zero_cnt<<<nblk_nodes, T>>>();
    k_hist<<<nblk_edges, T>>>(dst);
    k_scan_a<<<SCAN_NB, SCAN_BS>>>();
    k_scan_b<<<1, 1024>>>();
    k_scan_c<<<nblk_nodes, T>>>();
    k_fill<<<nblk_edges, T>>>(src, dst);

    // layer 1
    k_xform1<<<nblk_x1, T>>>(x, W1);
    k_agg32<<<nblk_rows8, T>>>();

    // layer 2
    k_xform2<<<nblk_rows8, T>>>(W2, b1);
    k_agg32<<<nblk_rows8, T>>>();

    // layer 3
    k_xform3<<<nblk_rowwarp, T>>>(W3, b2);
    k_agg1_final<<<nblk_nodes, T>>>(b3, out);
}

// round 5
// speedup vs baseline: 2.5370x; 1.0833x over previous
#include <cuda_runtime.h>
#include <math.h>

#define N_NODES 150000
#define N_EDGES 2400000
#define F_IN 128
#define HID 32
#define SCAN_BS 256
#define SCAN_NB ((N_NODES + SCAN_BS - 1) / SCAN_BS)   // 586

// Scratch (allocation-free rule: __device__ globals)
__device__ float g_dinv[N_NODES];
__device__ float g_tmp[(size_t)N_NODES * HID];
__device__ float g_acc[(size_t)N_NODES * HID];
__device__ float g_tmp3[N_NODES];
__device__ int   g_cnt[N_NODES];
__device__ int   g_rowptr[N_NODES + 1];
__device__ int   g_cursor[N_NODES];
__device__ int   g_bsum[1024];
__device__ int   g_boff[1024];
__device__ int   g_csr_src[N_EDGES];

// ---------------- CSR build ----------------
__global__ void k_zero_cnt() {
    int i = blockIdx.x * blockDim.x + threadIdx.x;
    if (i < N_NODES) g_cnt[i] = 0;
}

// 4 edges per thread (N_EDGES % 4 == 0)
__global__ void k_hist(const int* __restrict__ dst) {
    int t = blockIdx.x * blockDim.x + threadIdx.x;
    if (t * 4 < N_EDGES) {
        int4 d = __ldg((const int4*)dst + t);
        atomicAdd(&g_cnt[d.x], 1);
        atomicAdd(&g_cnt[d.y], 1);
        atomicAdd(&g_cnt[d.z], 1);
        atomicAdd(&g_cnt[d.w], 1);
    }
}

__global__ void k_scan_a() {
    __shared__ int wsum[8];
    int tid = threadIdx.x;
    int lane = tid & 31, w = tid >> 5;
    int i = blockIdx.x * SCAN_BS + tid;
    int v = (i < N_NODES) ? g_cnt[i] : 0;
    int s = v;
#pragma unroll
    for (int o = 1; o < 32; o <<= 1) {
        int t = __shfl_up_sync(0xffffffffu, s, o);
        if (lane >= o) s += t;
    }
    if (lane == 31) wsum[w] = s;
    __syncthreads();
    if (w == 0 && lane < 8) {
        int ws = wsum[lane];
#pragma unroll
        for (int o = 1; o < 8; o <<= 1) {
            int t = __shfl_up_sync(0xffu, ws, o);
            if (lane >= o) ws += t;
        }
        wsum[lane] = ws;
    }
    __syncthreads();
    int incl = s + (w > 0 ? wsum[w - 1] : 0);
    if (i < N_NODES) g_rowptr[i] = incl - v;   // block-local exclusive
    if (tid == SCAN_BS - 1) g_bsum[blockIdx.x] = incl;
}

__global__ void k_scan_b() {   // 1024 threads, scans SCAN_NB block sums
    __shared__ int wsum[32];
    int tid = threadIdx.x;
    int lane = tid & 31, w = tid >> 5;
    int v = (tid < SCAN_NB) ? g_bsum[tid] : 0;
    int s = v;
#pragma unroll
    for (int o = 1; o < 32; o <<= 1) {
        int t = __shfl_up_sync(0xffffffffu, s, o);
        if (lane >= o) s += t;
    }
    if (lane == 31) wsum[w] = s;
    __syncthreads();
    if (w == 0) {
        int ws = wsum[lane];
#pragma unroll
        for (int o = 1; o < 32; o <<= 1) {
            int t = __shfl_up_sync(0xffffffffu, ws, o);
            if (lane >= o) ws += t;
        }
        wsum[lane] = ws;
    }
    __syncthreads();
    if (tid < SCAN_NB) g_boff[tid] = s - v + (w > 0 ? wsum[w - 1] : 0);
}

__global__ void k_scan_c() {
    int i = blockIdx.x * blockDim.x + threadIdx.x;
    if (i < N_NODES) {
        int r = g_rowptr[i] + g_boff[i >> 8];
        g_rowptr[i] = r;
        g_cursor[i] = r;
        g_dinv[i] = rsqrtf((float)(g_cnt[i] + 1));  // +1 self loop, deg>=1
    }
    if (i == 0) g_rowptr[N_NODES] = N_EDGES;
}

__global__ void k_fill(const int* __restrict__ src, const int* __restrict__ dst) {
    int t = blockIdx.x * blockDim.x + threadIdx.x;
    if (t * 4 < N_EDGES) {
        int4 s = __ldg((const int4*)src + t);
        int4 d = __ldg((const int4*)dst + t);
        g_csr_src[atomicAdd(&g_cursor[d.x], 1)] = s.x;
        g_csr_src[atomicAdd(&g_cursor[d.y], 1)] = s.y;
        g_csr_src[atomicAdd(&g_cursor[d.z], 1)] = s.z;
        g_csr_src[atomicAdd(&g_cursor[d.w], 1)] = s.w;
    }
}

// ---------------- layer 1 transform: tmp = dinv * (x @ W1) ----------------
// 256 thr = 8 warps; each warp: 4 rows x 32 feats; block = 32 rows.
__global__ void k_xform1(const float* __restrict__ x, const float* __restrict__ W1) {
    __shared__ __align__(16) float sW[F_IN * HID];   // 16 KB
    __shared__ __align__(16) float sx[32 * F_IN];    // 16 KB
    int tid = threadIdx.x;
    int row0 = blockIdx.x * 32;

    {
        const float4* Wv = (const float4*)W1;
        float4* sWv = (float4*)sW;
        for (int i = tid; i < F_IN * HID / 4; i += 256) sWv[i] = Wv[i];
    }
    if (row0 + 32 <= N_NODES) {
        const float4* xv = (const float4*)(x + (size_t)row0 * F_IN);
        float4* sxv = (float4*)sx;
        for (int i = tid; i < 32 * F_IN / 4; i += 256) sxv[i] = xv[i];
    } else {
        for (int i = tid; i < 32 * F_IN; i += 256) {
            int r = i / F_IN;
            sx[i] = (row0 + r < N_NODES) ? x[(size_t)(row0 + r) * F_IN + (i % F_IN)] : 0.0f;
        }
    }
    __syncthreads();

    int w = tid >> 5, f = tid & 31;
    float acc0 = 0.f, acc1 = 0.f, acc2 = 0.f, acc3 = 0.f;
    const float* sx0 = &sx[(w * 4 + 0) * F_IN];
    const float* sx1 = &sx[(w * 4 + 1) * F_IN];
    const float* sx2 = &sx[(w * 4 + 2) * F_IN];
    const float* sx3 = &sx[(w * 4 + 3) * F_IN];
#pragma unroll
    for (int k4 = 0; k4 < F_IN; k4 += 4) {
        float4 xa = *(const float4*)(sx0 + k4);
        float4 xb = *(const float4*)(sx1 + k4);
        float4 xc = *(const float4*)(sx2 + k4);
        float4 xd = *(const float4*)(sx3 + k4);
        float w0 = sW[(k4 + 0) * HID + f];
        float w1 = sW[(k4 + 1) * HID + f];
        float w2 = sW[(k4 + 2) * HID + f];
        float w3 = sW[(k4 + 3) * HID + f];
        acc0 = fmaf(xa.x, w0, fmaf(xa.y, w1, fmaf(xa.z, w2, fmaf(xa.w, w3, acc0))));
        acc1 = fmaf(xb.x, w0, fmaf(xb.y, w1, fmaf(xb.z, w2, fmaf(xb.w, w3, acc1))));
        acc2 = fmaf(xc.x, w0, fmaf(xc.y, w1, fmaf(xc.z, w2, fmaf(xc.w, w3, acc2))));
        acc3 = fmaf(xd.x, w0, fmaf(xd.y, w1, fmaf(xd.z, w2, fmaf(xd.w, w3, acc3))));
    }
    float a[4] = {acc0, acc1, acc2, acc3};
#pragma unroll
    for (int j = 0; j < 4; j++) {
        int row = row0 + w * 4 + j;
        if (row < N_NODES) g_tmp[(size_t)row * HID + f] = g_dinv[row] * a[j];
    }
}

// ---------------- fused: agg(layer1) + relu + @W2 + scale -> g_acc ----------------
__global__ void k_agg_xf2(const float* __restrict__ W2, const float* __restrict__ b1) {
    __shared__ float sW[HID * HID];
    int tid = threadIdx.x;  // 256
    for (int i = tid; i < HID * HID; i += 256) sW[i] = W2[i];
    __syncthreads();
    int n = blockIdx.x * 8 + (tid >> 5);
    int lane = tid & 31;
    if (n >= N_NODES) return;  // warp-uniform
    int e = g_rowptr[n];
    int sE = g_rowptr[n + 1];
    float a = g_tmp[(size_t)n * HID + lane];  // self loop
    for (; e + 4 <= sE; e += 4) {
        int i0 = g_csr_src[e + 0];
        int i1 = g_csr_src[e + 1];
        int i2 = g_csr_src[e + 2];
        int i3 = g_csr_src[e + 3];
        float v0 = g_tmp[(size_t)i0 * HID + lane];
        float v1 = g_tmp[(size_t)i1 * HID + lane];
        float v2 = g_tmp[(size_t)i2 * HID + lane];
        float v3 = g_tmp[(size_t)i3 * HID + lane];
        a += (v0 + v1) + (v2 + v3);
    }
    for (; e < sE; e++) a += g_tmp[(size_t)g_csr_src[e] * HID + lane];
    float di = g_dinv[n];
    float y = fmaxf(fmaf(di, a, b1[lane]), 0.0f);
    float t = 0.0f;
#pragma unroll
    for (int k = 0; k < HID; k++)
        t = fmaf(__shfl_sync(0xffffffffu, y, k), sW[k * HID + lane], t);
    g_acc[(size_t)n * HID + lane] = di * t;
}

// ---------------- fused: agg(layer2) + relu + dot W3 + scale -> g_tmp3 ----------------
__global__ void k_agg_xf3(const float* __restrict__ W3, const float* __restrict__ b2) {
    int tid = threadIdx.x;
    int n = blockIdx.x * 8 + (tid >> 5);
    int lane = tid & 31;
    if (n >= N_NODES) return;  // warp-uniform
    int e = g_rowptr[n];
    int sE = g_rowptr[n + 1];
    float a = g_acc[(size_t)n * HID + lane];  // self loop
    for (; e + 4 <= sE; e += 4) {
        int i0 = g_csr_src[e + 0];
        int i1 = g_csr_src[e + 1];
        int i2 = g_csr_src[e + 2];
        int i3 = g_csr_src[e + 3];
        float v0 = g_acc[(size_t)i0 * HID + lane];
        float v1 = g_acc[(size_t)i1 * HID + lane];
        float v2 = g_acc[(size_t)i2 * HID + lane];
        float v3 = g_acc[(size_t)i3 * HID + lane];
        a += (v0 + v1) + (v2 + v3);
    }
    for (; e < sE; e++) a += g_acc[(size_t)g_csr_src[e] * HID + lane];
    float di = g_dinv[n];
    float y = fmaxf(fmaf(di, a, b2[lane]), 0.0f);
    float t = y * __ldg(&W3[lane]);
#pragma unroll
    for (int o = 16; o > 0; o >>= 1) t += __shfl_down_sync(0xffffffffu, t, o);
    if (lane == 0) g_tmp3[n] = di * t;
}

// ---------------- scalar gather + final sigmoid ----------------
__global__ void k_agg1_final(const float* __restrict__ b3, float* __restrict__ out) {
    int n = blockIdx.x * blockDim.x + threadIdx.x;
    if (n >= N_NODES) return;
    int e = g_rowptr[n];
    int sE = g_rowptr[n + 1];
    float a = g_tmp3[n];  // self loop
    for (; e + 4 <= sE; e += 4) {
        float v0 = g_tmp3[g_csr_src[e + 0]];
        float v1 = g_tmp3[g_csr_src[e + 1]];
        float v2 = g_tmp3[g_csr_src[e + 2]];
        float v3 = g_tmp3[g_csr_src[e + 3]];
        a += (v0 + v1) + (v2 + v3);
    }
    for (; e < sE; e++) a += g_tmp3[g_csr_src[e]];
    float z = fmaf(g_dinv[n], a, b3[0]);
    out[n] = 1.0f / (1.0f + __expf(-z));
}

extern "C" void kernel_launch(void* const* d_in, const int* in_sizes, int n_in,
                              void* d_out, int out_size) {
    // Resolve inputs by element count — robust to metadata ordering.
    int ix = -1, ie = -1, iw1 = -1, iw2 = -1, ib3 = -1;
    int i32[3], n32 = 0;
    for (int i = 0; i < n_in; i++) {
        switch (in_sizes[i]) {
            case 19200000: ix = i; break;
            case 4800000:  ie = i; break;
            case 4096:     iw1 = i; break;
            case 1024:     iw2 = i; break;
            case 1:        ib3 = i; break;
            case 32:       if (n32 < 3) i32[n32++] = i; break;
            default: break;
        }
    }
    int ib1, ib2, iw3;
    if (ie == 1) {  // dict order: x, edge_index, W1, b1, W2, b2, W3, b3
        ib1 = i32[0]; ib2 = i32[1]; iw3 = i32[2];
    } else {        // alphabetical: W1, W2, W3, b1, b2, b3, edge_index, x
        iw3 = i32[0]; ib1 = i32[1]; ib2 = i32[2];
    }

    const float* x  = (const float*)d_in[ix];
    const int* ei   = (const int*)d_in[ie];   // [2, E] int32
    const float* W1 = (const float*)d_in[iw1];
    const float* b1 = (const float*)d_in[ib1];
    const float* W2 = (const float*)d_in[iw2];
    const float* b2 = (const float*)d_in[ib2];
    const float* W3 = (const float*)d_in[iw3];
    const float* b3 = (const float*)d_in[ib3];
    float* out = (float*)d_out;

    const int* src = ei;
    const int* dst = ei + N_EDGES;

    const int T = 256;
    int nblk_nodes = (N_NODES + T - 1) / T;
    int nblk_edge4 = (N_EDGES / 4 + T - 1) / T;
    int nblk_x1 = (N_NODES + 31) / 32;
    int nblk_rows8 = (N_NODES + 7) / 8;

    // CSR build (+ degree normalization as byproduct)
    k_zero_cnt<<<nblk_nodes, T>>>();
    k_hist<<<nblk_edge4, T>>>(dst);
    k_scan_a<<<SCAN_NB, SCAN_BS>>>();
    k_scan_b<<<1, 1024>>>();
    k_scan_c<<<nblk_nodes, T>>>();
    k_fill<<<nblk_edge4, T>>>(src, dst);

    // layer 1 transform, then fused layers
    k_xform1<<<nblk_x1, T>>>(x, W1);
    k_agg_xf2<<<nblk_rows8, T>>>(W2, b1);    // agg L1 + relu + @W2
    k_agg_xf3<<<nblk_rows8, T>>>(W3, b2);    // agg L2 + relu + dot W3
    k_agg1_final<<<nblk_nodes, T>>>(b3, out);
}

// round 6
// speedup vs baseline: 2.5456x; 1.0034x over previous
#include <cuda_runtime.h>
#include <math.h>

#define N_NODES 150000
#define N_EDGES 2400000
#define F_IN 128
#define HID 32
#define SCAN_BS 256
#define SCAN_NB ((N_NODES + SCAN_BS - 1) / SCAN_BS)   // 586

#define EDGE_BLKS 2344        // ceil(600000/256) edge-quads
#define X1_BLKS 4688          // ceil(150000/32)
#define X1A_BLKS 2344         // first half of xform1 (rows [0, 75008))
#define X1B_BLKS 2344         // second half
#define SPLIT_ROWS (X1A_BLKS * 32)   // 75008
#define SCALE_BLKS 2344       // 75008*32/4/256 = 2344 exactly

// Scratch (allocation-free rule: __device__ globals)
__device__ float g_dinv[N_NODES];
__device__ float g_tmp[(size_t)N_NODES * HID];
__device__ float g_acc[(size_t)N_NODES * HID];
__device__ float g_tmp3[N_NODES];
__device__ int   g_cnt[N_NODES];
__device__ int   g_rowptr[N_NODES + 1];
__device__ int   g_cursor[N_NODES];
__device__ int   g_bsum[1024];
__device__ int   g_boff[1024];
__device__ int   g_csr_src[N_EDGES];

// ---------------- xform1 body: 32 rows starting at row0; optional inline dinv scale ----------------
__device__ __forceinline__ void xform1_body(
    const float* __restrict__ x, const float* __restrict__ W1,
    float* sW, float* sx, int row0, bool scale)
{
    int tid = threadIdx.x;
    {
        const float4* Wv = (const float4*)W1;
        float4* sWv = (float4*)sW;
        for (int i = tid; i < F_IN * HID / 4; i += 256) sWv[i] = Wv[i];
    }
    if (row0 + 32 <= N_NODES) {
        const float4* xv = (const float4*)(x + (size_t)row0 * F_IN);
        float4* sxv = (float4*)sx;
        for (int i = tid; i < 32 * F_IN / 4; i += 256) sxv[i] = xv[i];
    } else {
        for (int i = tid; i < 32 * F_IN; i += 256) {
            int r = i / F_IN;
            sx[i] = (row0 + r < N_NODES) ? x[(size_t)(row0 + r) * F_IN + (i % F_IN)] : 0.0f;
        }
    }
    __syncthreads();

    int w = tid >> 5, f = tid & 31;
    float acc0 = 0.f, acc1 = 0.f, acc2 = 0.f, acc3 = 0.f;
    const float* sx0 = &sx[(w * 4 + 0) * F_IN];
    const float* sx1 = &sx[(w * 4 + 1) * F_IN];
    const float* sx2 = &sx[(w * 4 + 2) * F_IN];
    const float* sx3 = &sx[(w * 4 + 3) * F_IN];
#pragma unroll
    for (int k4 = 0; k4 < F_IN; k4 += 4) {
        float4 xa = *(const float4*)(sx0 + k4);
        float4 xb = *(const float4*)(sx1 + k4);
        float4 xc = *(const float4*)(sx2 + k4);
        float4 xd = *(const float4*)(sx3 + k4);
        float w0 = sW[(k4 + 0) * HID + f];
        float w1 = sW[(k4 + 1) * HID + f];
        float w2 = sW[(k4 + 2) * HID + f];
        float w3 = sW[(k4 + 3) * HID + f];
        acc0 = fmaf(xa.x, w0, fmaf(xa.y, w1, fmaf(xa.z, w2, fmaf(xa.w, w3, acc0))));
        acc1 = fmaf(xb.x, w0, fmaf(xb.y, w1, fmaf(xb.z, w2, fmaf(xb.w, w3, acc1))));
        acc2 = fmaf(xc.x, w0, fmaf(xc.y, w1, fmaf(xc.z, w2, fmaf(xc.w, w3, acc2))));
        acc3 = fmaf(xd.x, w0, fmaf(xd.y, w1, fmaf(xd.z, w2, fmaf(xd.w, w3, acc3))));
    }
    float a[4] = {acc0, acc1, acc2, acc3};
#pragma unroll
    for (int j = 0; j < 4; j++) {
        int row = row0 + w * 4 + j;
        if (row < N_NODES) {
            float s = scale ? g_dinv[row] : 1.0f;
            g_tmp[(size_t)row * HID + f] = s * a[j];
        }
    }
}

// ---------------- F1: hist (edge quads) + xform1a (raw) ----------------
__global__ __launch_bounds__(256) void k_F1(const int* __restrict__ dst,
                                            const float* __restrict__ x,
                                            const float* __restrict__ W1) {
    __shared__ __align__(16) float sW[F_IN * HID];
    __shared__ __align__(16) float sx[32 * F_IN];
    if (blockIdx.x < EDGE_BLKS) {
        int t = blockIdx.x * 256 + threadIdx.x;
        if (t < N_EDGES / 4) {
            int4 d = __ldg((const int4*)dst + t);
            atomicAdd(&g_cnt[d.x], 1);
            atomicAdd(&g_cnt[d.y], 1);
            atomicAdd(&g_cnt[d.z], 1);
            atomicAdd(&g_cnt[d.w], 1);
        }
    } else {
        int xb = blockIdx.x - EDGE_BLKS;
        xform1_body(x, W1, sW, sx, xb * 32, false);
    }
}

// ---------------- scans ----------------
__global__ void k_scan_a() {
    __shared__ int wsum[8];
    int tid = threadIdx.x;
    int lane = tid & 31, w = tid >> 5;
    int i = blockIdx.x * SCAN_BS + tid;
    int v = (i < N_NODES) ? g_cnt[i] : 0;
    int s = v;
#pragma unroll
    for (int o = 1; o < 32; o <<= 1) {
        int t = __shfl_up_sync(0xffffffffu, s, o);
        if (lane >= o) s += t;
    }
    if (lane == 31) wsum[w] = s;
    __syncthreads();
    if (w == 0 && lane < 8) {
        int ws = wsum[lane];
#pragma unroll
        for (int o = 1; o < 8; o <<= 1) {
            int t = __shfl_up_sync(0xffu, ws, o);
            if (lane >= o) ws += t;
        }
        wsum[lane] = ws;
    }
    __syncthreads();
    int incl = s + (w > 0 ? wsum[w - 1] : 0);
    if (i < N_NODES) g_rowptr[i] = incl - v;
    if (tid == SCAN_BS - 1) g_bsum[blockIdx.x] = incl;
}

__global__ void k_scan_b() {
    __shared__ int wsum[32];
    int tid = threadIdx.x;
    int lane = tid & 31, w = tid >> 5;
    int v = (tid < SCAN_NB) ? g_bsum[tid] : 0;
    int s = v;
#pragma unroll
    for (int o = 1; o < 32; o <<= 1) {
        int t = __shfl_up_sync(0xffffffffu, s, o);
        if (lane >= o) s += t;
    }
    if (lane == 31) wsum[w] = s;
    __syncthreads();
    if (w == 0) {
        int ws = wsum[lane];
#pragma unroll
        for (int o = 1; o < 32; o <<= 1) {
            int t = __shfl_up_sync(0xffffffffu, ws, o);
            if (lane >= o) ws += t;
        }
        wsum[lane] = ws;
    }
    __syncthreads();
    if (tid < SCAN_NB) g_boff[tid] = s - v + (w > 0 ? wsum[w - 1] : 0);
}

__global__ void k_scan_c() {
    int i = blockIdx.x * blockDim.x + threadIdx.x;
    if (i < N_NODES) {
        int r = g_rowptr[i] + g_boff[i >> 8];
        g_rowptr[i] = r;
        g_cursor[i] = r;
        g_dinv[i] = rsqrtf((float)(g_cnt[i] + 1));  // +1 self loop
    }
    if (i == 0) g_rowptr[N_NODES] = N_EDGES;
}

// ---------------- F2: fill + xform1b (scaled) + scaleA for rows [0, SPLIT_ROWS) ----------------
__global__ __launch_bounds__(256) void k_F2(const int* __restrict__ src,
                                            const int* __restrict__ dst,
                                            const float* __restrict__ x,
                                            const float* __restrict__ W1) {
    __shared__ __align__(16) float sW[F_IN * HID];
    __shared__ __align__(16) float sx[32 * F_IN];
    if (blockIdx.x < EDGE_BLKS) {
        int t = blockIdx.x * 256 + threadIdx.x;
        if (t < N_EDGES / 4) {
            int4 s = __ldg((const int4*)src + t);
            int4 d = __ldg((const int4*)dst + t);
            g_csr_src[atomicAdd(&g_cursor[d.x], 1)] = s.x;
            g_csr_src[atomicAdd(&g_cursor[d.y], 1)] = s.y;
            g_csr_src[atomicAdd(&g_cursor[d.z], 1)] = s.z;
            g_csr_src[atomicAdd(&g_cursor[d.w], 1)] = s.w;
        }
    } else if (blockIdx.x < EDGE_BLKS + X1B_BLKS) {
        int xb = blockIdx.x - EDGE_BLKS;
        xform1_body(x, W1, sW, sx, SPLIT_ROWS + xb * 32, true);
    } else {
        // scale rows [0, SPLIT_ROWS): 600064 float4 over 2344 blocks, exact
        int i = (blockIdx.x - EDGE_BLKS - X1B_BLKS) * 256 + threadIdx.x;
        float4* tv = (float4*)g_tmp;
        float4 v = tv[i];
        float di = g_dinv[i >> 3];   // 8 float4 per 32-float row
        v.x *= di; v.y *= di; v.z *= di; v.w *= di;
        tv[i] = v;
    }
}

// ---------------- fused: agg(layer1) + relu + @W2 + scale -> g_acc ----------------
__global__ void k_agg_xf2(const float* __restrict__ W2, const float* __restrict__ b1) {
    __shared__ float sW[HID * HID];
    int tid = threadIdx.x;  // 256
    for (int i = tid; i < HID * HID; i += 256) sW[i] = W2[i];
    __syncthreads();
    int n = blockIdx.x * 8 + (tid >> 5);
    int lane = tid & 31;
    if (n >= N_NODES) return;  // warp-uniform
    int e = g_rowptr[n];
    int sE = g_rowptr[n + 1];
    float a = g_tmp[(size_t)n * HID + lane];  // self loop
    for (; e + 4 <= sE; e += 4) {
        int i0 = g_csr_src[e + 0];
        int i1 = g_csr_src[e + 1];
        int i2 = g_csr_src[e + 2];
        int i3 = g_csr_src[e + 3];
        float v0 = g_tmp[(size_t)i0 * HID + lane];
        float v1 = g_tmp[(size_t)i1 * HID + lane];
        float v2 = g_tmp[(size_t)i2 * HID + lane];
        float v3 = g_tmp[(size_t)i3 * HID + lane];
        a += (v0 + v1) + (v2 + v3);
    }
    for (; e < sE; e++) a += g_tmp[(size_t)g_csr_src[e] * HID + lane];
    float di = g_dinv[n];
    float y = fmaxf(fmaf(di, a, b1[lane]), 0.0f);
    float t = 0.0f;
#pragma unroll
    for (int k = 0; k < HID; k++)
        t = fmaf(__shfl_sync(0xffffffffu, y, k), sW[k * HID + lane], t);
    g_acc[(size_t)n * HID + lane] = di * t;
}

// ---------------- fused: agg(layer2) + relu + dot W3 + scale -> g_tmp3 ----------------
__global__ void k_agg_xf3(const float* __restrict__ W3, const float* __restrict__ b2) {
    int tid = threadIdx.x;
    int n = blockIdx.x * 8 + (tid >> 5);
    int lane = tid & 31;
    if (n >= N_NODES) return;  // warp-uniform
    int e = g_rowptr[n];
    int sE = g_rowptr[n + 1];
    float a = g_acc[(size_t)n * HID + lane];  // self loop
    for (; e + 4 <= sE; e += 4) {
        int i0 = g_csr_src[e + 0];
        int i1 = g_csr_src[e + 1];
        int i2 = g_csr_src[e + 2];
        int i3 = g_csr_src[e + 3];
        float v0 = g_acc[(size_t)i0 * HID + lane];
        float v1 = g_acc[(size_t)i1 * HID + lane];
        float v2 = g_acc[(size_t)i2 * HID + lane];
        float v3 = g_acc[(size_t)i3 * HID + lane];
        a += (v0 + v1) + (v2 + v3);
    }
    for (; e < sE; e++) a += g_acc[(size_t)g_csr_src[e] * HID + lane];
    float di = g_dinv[n];
    float y = fmaxf(fmaf(di, a, b2[lane]), 0.0f);
    float t = y * __ldg(&W3[lane]);
#pragma unroll
    for (int o = 16; o > 0; o >>= 1) t += __shfl_down_sync(0xffffffffu, t, o);
    if (lane == 0) g_tmp3[n] = di * t;
}

// ---------------- scalar gather + final sigmoid ----------------
__global__ void k_agg1_final(const float* __restrict__ b3, float* __restrict__ out) {
    int n = blockIdx.x * blockDim.x + threadIdx.x;
    if (n >= N_NODES) return;
    int e = g_rowptr[n];
    int sE = g_rowptr[n + 1];
    float a = g_tmp3[n];  // self loop
    for (; e + 4 <= sE; e += 4) {
        float v0 = g_tmp3[g_csr_src[e + 0]];
        float v1 = g_tmp3[g_csr_src[e + 1]];
        float v2 = g_tmp3[g_csr_src[e + 2]];
        float v3 = g_tmp3[g_csr_src[e + 3]];
        a += (v0 + v1) + (v2 + v3);
    }
    for (; e < sE; e++) a += g_tmp3[g_csr_src[e]];
    float z = fmaf(g_dinv[n], a, b3[0]);
    out[n] = 1.0f / (1.0f + __expf(-z));
}

extern "C" void kernel_launch(void* const* d_in, const int* in_sizes, int n_in,
                              void* d_out, int out_size) {
    // Resolve inputs by element count — robust to metadata ordering.
    int ix = -1, ie = -1, iw1 = -1, iw2 = -1, ib3 = -1;
    int i32[3], n32 = 0;
    for (int i = 0; i < n_in; i++) {
        switch (in_sizes[i]) {
            case 19200000: ix = i; break;
            case 4800000:  ie = i; break;
            case 4096:     iw1 = i; break;
            case 1024:     iw2 = i; break;
            case 1:        ib3 = i; break;
            case 32:       if (n32 < 3) i32[n32++] = i; break;
            default: break;
        }
    }
    int ib1, ib2, iw3;
    if (ie == 1) {  // dict order: x, edge_index, W1, b1, W2, b2, W3, b3
        ib1 = i32[0]; ib2 = i32[1]; iw3 = i32[2];
    } else {        // alphabetical: W1, W2, W3, b1, b2, b3, edge_index, x
        iw3 = i32[0]; ib1 = i32[1]; ib2 = i32[2];
    }

    const float* x  = (const float*)d_in[ix];
    const int* ei   = (const int*)d_in[ie];   // [2, E] int32
    const float* W1 = (const float*)d_in[iw1];
    const float* b1 = (const float*)d_in[ib1];
    const float* W2 = (const float*)d_in[iw2];
    const float* b2 = (const float*)d_in[ib2];
    const float* W3 = (const float*)d_in[iw3];
    const float* b3 = (const float*)d_in[ib3];
    float* out = (float*)d_out;

    const int* src = ei;
    const int* dst = ei + N_EDGES;

    const int T = 256;
    int nblk_nodes = (N_NODES + T - 1) / T;
    int nblk_rows8 = (N_NODES + 7) / 8;

    // zero counters via memset node (graph-capturable)
    void* cnt_ptr = nullptr;
    cudaGetSymbolAddress(&cnt_ptr, g_cnt);
    cudaMemsetAsync(cnt_ptr, 0, N_NODES * sizeof(int), 0);

    // F1: hist + xform1a (raw)  — overlapped heterogeneous kernel
    k_F1<<<EDGE_BLKS + X1A_BLKS, T>>>(dst, x, W1);
    k_scan_a<<<SCAN_NB, SCAN_BS>>>();
    k_scan_b<<<1, 1024>>>();
    k_scan_c<<<nblk_nodes, T>>>();
    // F2: fill + xform1b (scaled) + scaleA — overlapped heterogeneous kernel
    k_F2<<<EDGE_BLKS + X1B_BLKS + SCALE_BLKS, T>>>(src, dst, x, W1);

    k_agg_xf2<<<nblk_rows8, T>>>(W2, b1);    // agg L1 + relu + @W2
    k_agg_xf3<<<nblk_rows8, T>>>(W3, b2);    // agg L2 + relu + dot W3
    k_agg1_final<<<nblk_nodes, T>>>(b3, out);
}

// round 7
// speedup vs baseline: 2.7178x; 1.0677x over previous
#include <cuda_runtime.h>
#include <cuda_fp16.h>
#include <math.h>

#define N_NODES 150000
#define N_EDGES 2400000
#define F_IN 128
#define HID 32
#define SCAN_BS 256
#define SCAN_NB ((N_NODES + SCAN_BS - 1) / SCAN_BS)   // 586

#define EDGE_BLKS 2344        // 600000 edge-quads / 256
#define X1A_BLKS 2344         // rows [0, 75008)
#define X1B_BLKS 2344         // rows [75008, 150000)
#define SPLIT_ROWS 75008
#define SCALE_BLKS 1172       // 75008 rows * 64B / 16B / 256 = 1172 exactly

// Scratch (allocation-free rule: __device__ globals)
__device__ float  g_dinv[N_NODES];
__device__ __half g_tmp[(size_t)N_NODES * HID];    // fp16 messages (9.6 MB)
__device__ __half g_acc[(size_t)N_NODES * HID];
__device__ float  g_tmp3[N_NODES];
__device__ int    g_cnt[N_NODES];
__device__ int    g_rowptr[N_NODES + 1];
__device__ int    g_cursor[N_NODES];
__device__ int    g_bsum[1024];
__device__ int    g_csr_src[N_EDGES];

// ---------------- xform1 body: 32 rows starting at row0; optional inline dinv scale ----------------
__device__ __forceinline__ void xform1_body(
    const float* __restrict__ x, const float* __restrict__ W1,
    float* sW, float* sx, int row0, bool scale)
{
    int tid = threadIdx.x;
    {
        const float4* Wv = (const float4*)W1;
        float4* sWv = (float4*)sW;
        for (int i = tid; i < F_IN * HID / 4; i += 256) sWv[i] = Wv[i];
    }
    if (row0 + 32 <= N_NODES) {
        const float4* xv = (const float4*)(x + (size_t)row0 * F_IN);
        float4* sxv = (float4*)sx;
        for (int i = tid; i < 32 * F_IN / 4; i += 256) sxv[i] = xv[i];
    } else {
        for (int i = tid; i < 32 * F_IN; i += 256) {
            int r = i / F_IN;
            sx[i] = (row0 + r < N_NODES) ? x[(size_t)(row0 + r) * F_IN + (i % F_IN)] : 0.0f;
        }
    }
    __syncthreads();

    int w = tid >> 5, f = tid & 31;
    float acc0 = 0.f, acc1 = 0.f, acc2 = 0.f, acc3 = 0.f;
    const float* sx0 = &sx[(w * 4 + 0) * F_IN];
    const float* sx1 = &sx[(w * 4 + 1) * F_IN];
    const float* sx2 = &sx[(w * 4 + 2) * F_IN];
    const float* sx3 = &sx[(w * 4 + 3) * F_IN];
#pragma unroll
    for (int k4 = 0; k4 < F_IN; k4 += 4) {
        float4 xa = *(const float4*)(sx0 + k4);
        float4 xb = *(const float4*)(sx1 + k4);
        float4 xc = *(const float4*)(sx2 + k4);
        float4 xd = *(const float4*)(sx3 + k4);
        float w0 = sW[(k4 + 0) * HID + f];
        float w1 = sW[(k4 + 1) * HID + f];
        float w2 = sW[(k4 + 2) * HID + f];
        float w3 = sW[(k4 + 3) * HID + f];
        acc0 = fmaf(xa.x, w0, fmaf(xa.y, w1, fmaf(xa.z, w2, fmaf(xa.w, w3, acc0))));
        acc1 = fmaf(xb.x, w0, fmaf(xb.y, w1, fmaf(xb.z, w2, fmaf(xb.w, w3, acc1))));
        acc2 = fmaf(xc.x, w0, fmaf(xc.y, w1, fmaf(xc.z, w2, fmaf(xc.w, w3, acc2))));
        acc3 = fmaf(xd.x, w0, fmaf(xd.y, w1, fmaf(xd.z, w2, fmaf(xd.w, w3, acc3))));
    }
    float a[4] = {acc0, acc1, acc2, acc3};
#pragma unroll
    for (int j = 0; j < 4; j++) {
        int row = row0 + w * 4 + j;
        if (row < N_NODES) {
            float s = scale ? g_dinv[row] : 1.0f;
            g_tmp[(size_t)row * HID + f] = __float2half_rn(s * a[j]);
        }
    }
}

// ---------------- F1: interleaved hist (even blocks) + xform1a raw (odd blocks) ----------------
__global__ __launch_bounds__(256) void k_F1(const int* __restrict__ dst,
                                            const float* __restrict__ x,
                                            const float* __restrict__ W1) {
    __shared__ __align__(16) float sW[F_IN * HID];
    __shared__ __align__(16) float sx[32 * F_IN];
    int half_idx = blockIdx.x >> 1;
    if ((blockIdx.x & 1) == 0) {
        int t = half_idx * 256 + threadIdx.x;
        if (t < N_EDGES / 4) {
            int4 d = __ldg((const int4*)dst + t);
            atomicAdd(&g_cnt[d.x], 1);
            atomicAdd(&g_cnt[d.y], 1);
            atomicAdd(&g_cnt[d.z], 1);
            atomicAdd(&g_cnt[d.w], 1);
        }
    } else {
        xform1_body(x, W1, sW, sx, half_idx * 32, false);
    }
}

// ---------------- scan A: per-block exclusive prefix of cnt ----------------
__global__ void k_scan_a() {
    __shared__ int wsum[8];
    int tid = threadIdx.x;
    int lane = tid & 31, w = tid >> 5;
    int i = blockIdx.x * SCAN_BS + tid;
    int v = (i < N_NODES) ? g_cnt[i] : 0;
    int s = v;
#pragma unroll
    for (int o = 1; o < 32; o <<= 1) {
        int t = __shfl_up_sync(0xffffffffu, s, o);
        if (lane >= o) s += t;
    }
    if (lane == 31) wsum[w] = s;
    __syncthreads();
    if (w == 0 && lane < 8) {
        int ws = wsum[lane];
#pragma unroll
        for (int o = 1; o < 8; o <<= 1) {
            int t = __shfl_up_sync(0xffu, ws, o);
            if (lane >= o) ws += t;
        }
        wsum[lane] = ws;
    }
    __syncthreads();
    int incl = s + (w > 0 ? wsum[w - 1] : 0);
    if (i < N_NODES) g_rowptr[i] = incl - v;
    if (tid == SCAN_BS - 1) g_bsum[blockIdx.x] = incl;
}

// ---------------- scan C (fused with B): each block sums bsum[0..blk) itself ----------------
__global__ void k_scan_c() {
    __shared__ int red[8];
    __shared__ int s_off;
    int tid = threadIdx.x;
    int lane = tid & 31, w = tid >> 5;
    int blk = blockIdx.x;
    // partial sum of bsum[j] for j < blk, strided
    int p = 0;
    for (int j = tid; j < blk; j += 256) p += g_bsum[j];
#pragma unroll
    for (int o = 16; o > 0; o >>= 1) p += __shfl_down_sync(0xffffffffu, p, o);
    if (lane == 0) red[w] = p;
    __syncthreads();
    if (tid == 0) {
        int t = 0;
#pragma unroll
        for (int k = 0; k < 8; k++) t += red[k];
        s_off = t;
    }
    __syncthreads();
    int off = s_off;
    int i = blk * 256 + tid;
    if (i < N_NODES) {
        int r = g_rowptr[i] + off;
        g_rowptr[i] = r;
        g_cursor[i] = r;
        g_dinv[i] = rsqrtf((float)(g_cnt[i] + 1));  // +1 self loop
    }
    if (i == 0) g_rowptr[N_NODES] = N_EDGES;
}

// ---------------- F2: interleaved fill + xform1b (scaled), then scaleA blocks ----------------
__global__ __launch_bounds__(256) void k_F2(const int* __restrict__ src,
                                            const int* __restrict__ dst,
                                            const float* __restrict__ x,
                                            const float* __restrict__ W1) {
    __shared__ __align__(16) float sW[F_IN * HID];
    __shared__ __align__(16) float sx[32 * F_IN];
    if (blockIdx.x < 2 * EDGE_BLKS) {
        int half_idx = blockIdx.x >> 1;
        if ((blockIdx.x & 1) == 0) {
            int t = half_idx * 256 + threadIdx.x;
            if (t < N_EDGES / 4) {
                int4 s = __ldg((const int4*)src + t);
                int4 d = __ldg((const int4*)dst + t);
                g_csr_src[atomicAdd(&g_cursor[d.x], 1)] = s.x;
                g_csr_src[atomicAdd(&g_cursor[d.y], 1)] = s.y;
                g_csr_src[atomicAdd(&g_cursor[d.z], 1)] = s.z;
                g_csr_src[atomicAdd(&g_cursor[d.w], 1)] = s.w;
            }
        } else {
            xform1_body(x, W1, sW, sx, SPLIT_ROWS + half_idx * 32, true);
        }
    } else {
        // scale raw rows [0, SPLIT_ROWS): 16B (8 half) per thread; 300032 int4 total
        int i = (blockIdx.x - 2 * EDGE_BLKS) * 256 + threadIdx.x;
        int4* tv = (int4*)g_tmp;
        int4 raw = tv[i];
        float di = g_dinv[i >> 2];   // 4 int4 per 32-half row
        __half2* h = (__half2*)&raw;
        __half2 d2 = __float2half2_rn(di);
#pragma unroll
        for (int k = 0; k < 4; k++) h[k] = __hmul2(h[k], d2);
        tv[i] = raw;
    }
}

// ---------------- fused: agg(layer1) + relu + @W2 + scale -> g_acc (fp16) ----------------
__global__ void k_agg_xf2(const float* __restrict__ W2, const float* __restrict__ b1) {
    __shared__ float sW[HID * HID];
    int tid = threadIdx.x;  // 256
    for (int i = tid; i < HID * HID; i += 256) sW[i] = W2[i];
    __syncthreads();
    int n = blockIdx.x * 8 + (tid >> 5);
    int lane = tid & 31;
    if (n >= N_NODES) return;  // warp-uniform
    int e = g_rowptr[n];
    int sE = g_rowptr[n + 1];
    float a = __half2float(g_tmp[(size_t)n * HID + lane]);  // self loop
    for (; e + 4 <= sE; e += 4) {
        int i0 = g_csr_src[e + 0];
        int i1 = g_csr_src[e + 1];
        int i2 = g_csr_src[e + 2];
        int i3 = g_csr_src[e + 3];
        float v0 = __half2float(g_tmp[(size_t)i0 * HID + lane]);
        float v1 = __half2float(g_tmp[(size_t)i1 * HID + lane]);
        float v2 = __half2float(g_tmp[(size_t)i2 * HID + lane]);
        float v3 = __half2float(g_tmp[(size_t)i3 * HID + lane]);
        a += (v0 + v1) + (v2 + v3);
    }
    for (; e < sE; e++) a += __half2float(g_tmp[(size_t)g_csr_src[e] * HID + lane]);
    float di = g_dinv[n];
    float y = fmaxf(fmaf(di, a, b1[lane]), 0.0f);
    float t = 0.0f;
#pragma unroll
    for (int k = 0; k < HID; k++)
        t = fmaf(__shfl_sync(0xffffffffu, y, k), sW[k * HID + lane], t);
    g_acc[(size_t)n * HID + lane] = __float2half_rn(di * t);
}

// ---------------- fused: agg(layer2) + relu + dot W3 + scale -> g_tmp3 ----------------
__global__ void k_agg_xf3(const float* __restrict__ W3, const float* __restrict__ b2) {
    int tid = threadIdx.x;
    int n = blockIdx.x * 8 + (tid >> 5);
    int lane = tid & 31;
    if (n >= N_NODES) return;  // warp-uniform
    int e = g_rowptr[n];
    int sE = g_rowptr[n + 1];
    float a = __half2float(g_acc[(size_t)n * HID + lane]);  // self loop
    for (; e + 4 <= sE; e += 4) {
        int i0 = g_csr_src[e + 0];
        int i1 = g_csr_src[e + 1];
        int i2 = g_csr_src[e + 2];
        int i3 = g_csr_src[e + 3];
        float v0 = __half2float(g_acc[(size_t)i0 * HID + lane]);
        float v1 = __half2float(g_acc[(size_t)i1 * HID + lane]);
        float v2 = __half2float(g_acc[(size_t)i2 * HID + lane]);
        float v3 = __half2float(g_acc[(size_t)i3 * HID + lane]);
        a += (v0 + v1) + (v2 + v3);
    }
    for (; e < sE; e++) a += __half2float(g_acc[(size_t)g_csr_src[e] * HID + lane]);
    float di = g_dinv[n];
    float y = fmaxf(fmaf(di, a, b2[lane]), 0.0f);
    float t = y * __ldg(&W3[lane]);
#pragma unroll
    for (int o = 16; o > 0; o >>= 1) t += __shfl_down_sync(0xffffffffu, t, o);
    if (lane == 0) g_tmp3[n] = di * t;
}

// ---------------- scalar gather + final sigmoid ----------------
__global__ void k_agg1_final(const float* __restrict__ b3, float* __restrict__ out) {
    int n = blockIdx.x * blockDim.x + threadIdx.x;
    if (n >= N_NODES) return;
    int e = g_rowptr[n];
    int sE = g_rowptr[n + 1];
    float a = g_tmp3[n];  // self loop
    for (; e + 4 <= sE; e += 4) {
        float v0 = g_tmp3[g_csr_src[e + 0]];
        float v1 = g_tmp3[g_csr_src[e + 1]];
        float v2 = g_tmp3[g_csr_src[e + 2]];
        float v3 = g_tmp3[g_csr_src[e + 3]];
        a += (v0 + v1) + (v2 + v3);
    }
    for (; e < sE; e++) a += g_tmp3[g_csr_src[e]];
    float z = fmaf(g_dinv[n], a, b3[0]);
    out[n] = 1.0f / (1.0f + __expf(-z));
}

extern "C" void kernel_launch(void* const* d_in, const int* in_sizes, int n_in,
                              void* d_out, int out_size) {
    // Resolve inputs by element count — robust to metadata ordering.
    int ix = -1, ie = -1, iw1 = -1, iw2 = -1, ib3 = -1;
    int i32[3], n32 = 0;
    for (int i = 0; i < n_in; i++) {
        switch (in_sizes[i]) {
            case 19200000: ix = i; break;
            case 4800000:  ie = i; break;
            case 4096:     iw1 = i; break;
            case 1024:     iw2 = i; break;
            case 1:        ib3 = i; break;
            case 32:       if (n32 < 3) i32[n32++] = i; break;
            default: break;
        }
    }
    int ib1, ib2, iw3;
    if (ie == 1) {  // dict order: x, edge_index, W1, b1, W2, b2, W3, b3
        ib1 = i32[0]; ib2 = i32[1]; iw3 = i32[2];
    } else {        // alphabetical: W1, W2, W3, b1, b2, b3, edge_index, x
        iw3 = i32[0]; ib1 = i32[1]; ib2 = i32[2];
    }

    const float* x  = (const float*)d_in[ix];
    const int* ei   = (const int*)d_in[ie];   // [2, E] int32
    const float* W1 = (const float*)d_in[iw1];
    const float* b1 = (const float*)d_in[ib1];
    const float* W2 = (const float*)d_in[iw2];
    const float* b2 = (const float*)d_in[ib2];
    const float* W3 = (const float*)d_in[iw3];
    const float* b3 = (const float*)d_in[ib3];
    float* out = (float*)d_out;

    const int* src = ei;
    const int* dst = ei + N_EDGES;

    const int T = 256;
    int nblk_nodes = (N_NODES + T - 1) / T;
    int nblk_rows8 = (N_NODES + 7) / 8;

    // zero counters via memset node (graph-capturable)
    void* cnt_ptr = nullptr;
    cudaGetSymbolAddress(&cnt_ptr, g_cnt);
    cudaMemsetAsync(cnt_ptr, 0, N_NODES * sizeof(int), 0);

    // F1: interleaved hist + xform1a (raw)
    k_F1<<<2 * EDGE_BLKS, T>>>(dst, x, W1);
    k_scan_a<<<SCAN_NB, SCAN_BS>>>();
    k_scan_c<<<SCAN_NB, SCAN_BS>>>();   // fused scan_b + scan_c
    // F2: interleaved fill + xform1b (scaled), then scale pass for rows [0, SPLIT)
    k_F2<<<2 * EDGE_BLKS + SCALE_BLKS, T>>>(src, dst, x, W1);

    k_agg_xf2<<<nblk_rows8, T>>>(W2, b1);    // agg L1 + relu + @W2
    k_agg_xf3<<<nblk_rows8, T>>>(W3, b2);    // agg L2 + relu + dot W3
    k_agg1_final<<<nblk_nodes, T>>>(b3, out);
}

// round 8
// speedup vs baseline: 3.0494x; 1.1220x over previous
#include <cuda_runtime.h>
#include <cuda_fp16.h>
#include <math.h>

#define N_NODES 150000
#define N_EDGES 2400000
#define F_IN 128
#define HID 32
#define SCAN_BS 256
#define SCAN_NB ((N_NODES + SCAN_BS - 1) / SCAN_BS)   // 586

#define EDGE_BLKS 2344        // 600000 edge-quads / 256 (rounded up)
#define X1_BLKS 2344          // ceil(150000/64) rows, 64 rows/block
#define SCALE_THREADS 600000  // 150000 rows * 32 half / 8 half-per-thread
#define SCALE_BLKS 2344       // ceil(600000/256)

// Scratch (allocation-free rule: __device__ globals)
__device__ float  g_dinv[N_NODES];
__device__ __half g_tmp[(size_t)N_NODES * HID];    // fp16 messages (9.6 MB)
__device__ __half g_acc[(size_t)N_NODES * HID];
__device__ float  g_tmp3[N_NODES];
__device__ int    g_cnt[N_NODES];
__device__ int    g_rowptr[N_NODES + 1];
__device__ int    g_cursor[N_NODES];
__device__ int    g_bsum[1024];
__device__ int    g_csr_src[N_EDGES];

// ---------------- xform1 body: 64 rows/block, 8 rows/thread, raw (no dinv) ----------------
__device__ __forceinline__ void xform1_body8(
    const float* __restrict__ x, const float* __restrict__ W1,
    float* sW, float* sx, int row0)
{
    int tid = threadIdx.x;
    {
        const float4* Wv = (const float4*)W1;
        float4* sWv = (float4*)sW;
#pragma unroll
        for (int i = 0; i < 4; i++) sWv[tid + i * 256] = Wv[tid + i * 256];
    }
    if (row0 + 64 <= N_NODES) {
        const float4* xv = (const float4*)(x + (size_t)row0 * F_IN);
        float4* sxv = (float4*)sx;
#pragma unroll
        for (int i = 0; i < 8; i++) sxv[tid + i * 256] = xv[tid + i * 256];
    } else {
        for (int i = tid; i < 64 * F_IN; i += 256) {
            int r = i >> 7;
            sx[i] = (row0 + r < N_NODES) ? x[(size_t)(row0 + r) * F_IN + (i & 127)] : 0.0f;
        }
    }
    __syncthreads();

    int w = tid >> 5, f = tid & 31;
    float acc[8] = {0, 0, 0, 0, 0, 0, 0, 0};
    const float* xr = &sx[(w * 8) * F_IN];
#pragma unroll
    for (int k4 = 0; k4 < F_IN; k4 += 4) {
        float w0 = sW[(k4 + 0) * HID + f];
        float w1 = sW[(k4 + 1) * HID + f];
        float w2 = sW[(k4 + 2) * HID + f];
        float w3 = sW[(k4 + 3) * HID + f];
#pragma unroll
        for (int r = 0; r < 8; r++) {
            float4 xa = *(const float4*)(xr + r * F_IN + k4);
            acc[r] = fmaf(xa.x, w0, fmaf(xa.y, w1, fmaf(xa.z, w2, fmaf(xa.w, w3, acc[r]))));
        }
    }
#pragma unroll
    for (int r = 0; r < 8; r++) {
        int row = row0 + w * 8 + r;
        if (row < N_NODES) g_tmp[(size_t)row * HID + f] = __float2half_rn(acc[r]);
    }
}

// ---------------- F1: interleaved hist (even blocks) + xform1 raw (odd blocks) ----------------
__global__ __launch_bounds__(256) void k_F1(const int* __restrict__ dst,
                                            const float* __restrict__ x,
                                            const float* __restrict__ W1) {
    __shared__ __align__(16) float sW[F_IN * HID];   // 16 KB
    __shared__ __align__(16) float sx[64 * F_IN];    // 32 KB
    int half_idx = blockIdx.x >> 1;
    if ((blockIdx.x & 1) == 0) {
        int t = half_idx * 256 + threadIdx.x;
        if (t < N_EDGES / 4) {
            int4 d = __ldg((const int4*)dst + t);
            atomicAdd(&g_cnt[d.x], 1);
            atomicAdd(&g_cnt[d.y], 1);
            atomicAdd(&g_cnt[d.z], 1);
            atomicAdd(&g_cnt[d.w], 1);
        }
    } else {
        xform1_body8(x, W1, sW, sx, half_idx * 64);
    }
}

// ---------------- scan A ----------------
__global__ void k_scan_a() {
    __shared__ int wsum[8];
    int tid = threadIdx.x;
    int lane = tid & 31, w = tid >> 5;
    int i = blockIdx.x * SCAN_BS + tid;
    int v = (i < N_NODES) ? g_cnt[i] : 0;
    int s = v;
#pragma unroll
    for (int o = 1; o < 32; o <<= 1) {
        int t = __shfl_up_sync(0xffffffffu, s, o);
        if (lane >= o) s += t;
    }
    if (lane == 31) wsum[w] = s;
    __syncthreads();
    if (w == 0 && lane < 8) {
        int ws = wsum[lane];
#pragma unroll
        for (int o = 1; o < 8; o <<= 1) {
            int t = __shfl_up_sync(0xffu, ws, o);
            if (lane >= o) ws += t;
        }
        wsum[lane] = ws;
    }
    __syncthreads();
    int incl = s + (w > 0 ? wsum[w - 1] : 0);
    if (i < N_NODES) g_rowptr[i] = incl - v;
    if (tid == SCAN_BS - 1) g_bsum[blockIdx.x] = incl;
}

// ---------------- scan C (fused B): each block sums bsum[0..blk) itself ----------------
__global__ void k_scan_c() {
    __shared__ int red[8];
    __shared__ int s_off;
    int tid = threadIdx.x;
    int lane = tid & 31, w = tid >> 5;
    int blk = blockIdx.x;
    int p = 0;
    for (int j = tid; j < blk; j += 256) p += g_bsum[j];
#pragma unroll
    for (int o = 16; o > 0; o >>= 1) p += __shfl_down_sync(0xffffffffu, p, o);
    if (lane == 0) red[w] = p;
    __syncthreads();
    if (tid == 0) {
        int t = 0;
#pragma unroll
        for (int k = 0; k < 8; k++) t += red[k];
        s_off = t;
    }
    __syncthreads();
    int off = s_off;
    int i = blk * 256 + tid;
    if (i < N_NODES) {
        int r = g_rowptr[i] + off;
        g_rowptr[i] = r;
        g_cursor[i] = r;
        g_dinv[i] = rsqrtf((float)(g_cnt[i] + 1));  // +1 self loop
    }
    if (i == 0) g_rowptr[N_NODES] = N_EDGES;
}

// ---------------- F2: interleaved fill (even) + dinv-scale of g_tmp (odd) ----------------
__global__ __launch_bounds__(256) void k_F2(const int* __restrict__ src,
                                            const int* __restrict__ dst) {
    int half_idx = blockIdx.x >> 1;
    if ((blockIdx.x & 1) == 0) {
        int t = half_idx * 256 + threadIdx.x;
        if (t < N_EDGES / 4) {
            int4 s = __ldg((const int4*)src + t);
            int4 d = __ldg((const int4*)dst + t);
            g_csr_src[atomicAdd(&g_cursor[d.x], 1)] = s.x;
            g_csr_src[atomicAdd(&g_cursor[d.y], 1)] = s.y;
            g_csr_src[atomicAdd(&g_cursor[d.z], 1)] = s.z;
            g_csr_src[atomicAdd(&g_cursor[d.w], 1)] = s.w;
        }
    } else {
        int i = half_idx * 256 + threadIdx.x;   // 8 halves (16B) per thread
        if (i < SCALE_THREADS) {
            int4* tv = (int4*)g_tmp;
            int4 raw = tv[i];
            float di = g_dinv[i >> 2];   // 4 int4 per 32-half row
            __half2* h = (__half2*)&raw;
            __half2 d2 = __float2half2_rn(di);
#pragma unroll
            for (int k = 0; k < 4; k++) h[k] = __hmul2(h[k], d2);
            tv[i] = raw;
        }
    }
}

// ---------------- fused: agg(L1) + relu + @W2 + scale -> g_acc (fp16) ----------------
// 4 edges per warp-iteration: lane = eidx*8 + fg; each lane loads int2 (4 halves).
__global__ void k_agg_xf2(const float* __restrict__ W2, const float* __restrict__ b1) {
    __shared__ float sW[HID * HID];
    __shared__ float sy[8][HID];
    int tid = threadIdx.x;  // 256
    for (int i = tid; i < HID * HID; i += 256) sW[i] = W2[i];
    __syncthreads();
    int w = tid >> 5, lane = tid & 31;
    int n = blockIdx.x * 8 + w;
    if (n >= N_NODES) return;  // warp-uniform
    int eidx = lane >> 3, fg = lane & 7;
    int e = g_rowptr[n];
    int e1 = g_rowptr[n + 1];
    float ax = 0.f, ay = 0.f, az = 0.f, aw = 0.f;
    for (; e + 4 <= e1; e += 4) {
        int s = g_csr_src[e + eidx];
        int2 v = *(const int2*)(g_tmp + (size_t)s * HID + fg * 4);
        float2 f0 = __half22float2(*(__half2*)&v.x);
        float2 f1 = __half22float2(*(__half2*)&v.y);
        ax += f0.x; ay += f0.y; az += f1.x; aw += f1.y;
    }
    if (eidx < e1 - e) {
        int s = g_csr_src[e + eidx];
        int2 v = *(const int2*)(g_tmp + (size_t)s * HID + fg * 4);
        float2 f0 = __half22float2(*(__half2*)&v.x);
        float2 f1 = __half22float2(*(__half2*)&v.y);
        ax += f0.x; ay += f0.y; az += f1.x; aw += f1.y;
    }
#pragma unroll
    for (int o = 8; o <= 16; o <<= 1) {
        ax += __shfl_xor_sync(0xffffffffu, ax, o);
        ay += __shfl_xor_sync(0xffffffffu, ay, o);
        az += __shfl_xor_sync(0xffffffffu, az, o);
        aw += __shfl_xor_sync(0xffffffffu, aw, o);
    }
    // self loop
    {
        int2 v = *(const int2*)(g_tmp + (size_t)n * HID + fg * 4);
        float2 f0 = __half22float2(*(__half2*)&v.x);
        float2 f1 = __half22float2(*(__half2*)&v.y);
        ax += f0.x; ay += f0.y; az += f1.x; aw += f1.y;
    }
    float di = g_dinv[n];
    float4 bv = *(const float4*)(b1 + fg * 4);
    float4 y;
    y.x = fmaxf(fmaf(di, ax, bv.x), 0.0f);
    y.y = fmaxf(fmaf(di, ay, bv.y), 0.0f);
    y.z = fmaxf(fmaf(di, az, bv.z), 0.0f);
    y.w = fmaxf(fmaf(di, aw, bv.w), 0.0f);
    if (eidx == 0) *(float4*)&sy[w][fg * 4] = y;
    __syncwarp();
    float t = 0.0f;
#pragma unroll
    for (int k = 0; k < HID; k++) t = fmaf(sy[w][k], sW[k * HID + lane], t);
    g_acc[(size_t)n * HID + lane] = __float2half_rn(di * t);
}

// ---------------- fused: agg(L2) + relu + dot W3 + scale -> g_tmp3 ----------------
__global__ void k_agg_xf3(const float* __restrict__ W3, const float* __restrict__ b2) {
    int tid = threadIdx.x;
    int w = tid >> 5, lane = tid & 31;
    int n = blockIdx.x * 8 + w;
    if (n >= N_NODES) return;  // warp-uniform
    int eidx = lane >> 3, fg = lane & 7;
    int e = g_rowptr[n];
    int e1 = g_rowptr[n + 1];
    float ax = 0.f, ay = 0.f, az = 0.f, aw = 0.f;
    for (; e + 4 <= e1; e += 4) {
        int s = g_csr_src[e + eidx];
        int2 v = *(const int2*)(g_acc + (size_t)s * HID + fg * 4);
        float2 f0 = __half22float2(*(__half2*)&v.x);
        float2 f1 = __half22float2(*(__half2*)&v.y);
        ax += f0.x; ay += f0.y; az += f1.x; aw += f1.y;
    }
    if (eidx < e1 - e) {
        int s = g_csr_src[e + eidx];
        int2 v = *(const int2*)(g_acc + (size_t)s * HID + fg * 4);
        float2 f0 = __half22float2(*(__half2*)&v.x);
        float2 f1 = __half22float2(*(__half2*)&v.y);
        ax += f0.x; ay += f0.y; az += f1.x; aw += f1.y;
    }
#pragma unroll
    for (int o = 8; o <= 16; o <<= 1) {
        ax += __shfl_xor_sync(0xffffffffu, ax, o);
        ay += __shfl_xor_sync(0xffffffffu, ay, o);
        az += __shfl_xor_sync(0xffffffffu, az, o);
        aw += __shfl_xor_sync(0xffffffffu, aw, o);
    }
    {
        int2 v = *(const int2*)(g_acc + (size_t)n * HID + fg * 4);
        float2 f0 = __half22float2(*(__half2*)&v.x);
        float2 f1 = __half22float2(*(__half2*)&v.y);
        ax += f0.x; ay += f0.y; az += f1.x; aw += f1.y;
    }
    float di = g_dinv[n];
    float4 bv = *(const float4*)(b2 + fg * 4);
    float4 wv = *(const float4*)(W3 + fg * 4);
    float t = fmaxf(fmaf(di, ax, bv.x), 0.0f) * wv.x
            + fmaxf(fmaf(di, ay, bv.y), 0.0f) * wv.y
            + fmaxf(fmaf(di, az, bv.z), 0.0f) * wv.z
            + fmaxf(fmaf(di, aw, bv.w), 0.0f) * wv.w;
#pragma unroll
    for (int o = 1; o <= 4; o <<= 1) t += __shfl_xor_sync(0xffffffffu, t, o);
    if (lane == 0) g_tmp3[n] = di * t;
}

// ---------------- scalar gather + final sigmoid ----------------
__global__ void k_agg1_final(const float* __restrict__ b3, float* __restrict__ out) {
    int n = blockIdx.x * blockDim.x + threadIdx.x;
    if (n >= N_NODES) return;
    int e = g_rowptr[n];
    int e1 = g_rowptr[n + 1];
    float a = g_tmp3[n];  // self loop
    for (; e + 4 <= e1; e += 4) {
        float v0 = g_tmp3[g_csr_src[e + 0]];
        float v1 = g_tmp3[g_csr_src[e + 1]];
        float v2 = g_tmp3[g_csr_src[e + 2]];
        float v3 = g_tmp3[g_csr_src[e + 3]];
        a += (v0 + v1) + (v2 + v3);
    }
    for (; e < e1; e++) a += g_tmp3[g_csr_src[e]];
    float z = fmaf(g_dinv[n], a, b3[0]);
    out[n] = 1.0f / (1.0f + __expf(-z));
}

extern "C" void kernel_launch(void* const* d_in, const int* in_sizes, int n_in,
                              void* d_out, int out_size) {
    // Resolve inputs by element count — robust to metadata ordering.
    int ix = -1, ie = -1, iw1 = -1, iw2 = -1, ib3 = -1;
    int i32[3], n32 = 0;
    for (int i = 0; i < n_in; i++) {
        switch (in_sizes[i]) {
            case 19200000: ix = i; break;
            case 4800000:  ie = i; break;
            case 4096:     iw1 = i; break;
            case 1024:     iw2 = i; break;
            case 1:        ib3 = i; break;
            case 32:       if (n32 < 3) i32[n32++] = i; break;
            default: break;
        }
    }
    int ib1, ib2, iw3;
    if (ie == 1) {  // dict order: x, edge_index, W1, b1, W2, b2, W3, b3
        ib1 = i32[0]; ib2 = i32[1]; iw3 = i32[2];
    } else {        // alphabetical: W1, W2, W3, b1, b2, b3, edge_index, x
        iw3 = i32[0]; ib1 = i32[1]; ib2 = i32[2];
    }

    const float* x  = (const float*)d_in[ix];
    const int* ei   = (const int*)d_in[ie];   // [2, E] int32
    const float* W1 = (const float*)d_in[iw1];
    const float* b1 = (const float*)d_in[ib1];
    const float* W2 = (const float*)d_in[iw2];
    const float* b2 = (const float*)d_in[ib2];
    const float* W3 = (const float*)d_in[iw3];
    const float* b3 = (const float*)d_in[ib3];
    float* out = (float*)d_out;

    const int* src = ei;
    const int* dst = ei + N_EDGES;

    const int T = 256;
    int nblk_nodes = (N_NODES + T - 1) / T;
    int nblk_rows8 = (N_NODES + 7) / 8;

    // zero counters via memset node (graph-capturable)
    void* cnt_ptr = nullptr;
    cudaGetSymbolAddress(&cnt_ptr, g_cnt);
    cudaMemsetAsync(cnt_ptr, 0, N_NODES * sizeof(int), 0);

    // F1: interleaved hist + full xform1 (raw)
    k_F1<<<EDGE_BLKS + X1_BLKS, T>>>(dst, x, W1);
    k_scan_a<<<SCAN_NB, SCAN_BS>>>();
    k_scan_c<<<SCAN_NB, SCAN_BS>>>();   // fused scan_b + scan_c
    // F2: interleaved fill + dinv scale of g_tmp
    k_F2<<<EDGE_BLKS + SCALE_BLKS, T>>>(src, dst);

    k_agg_xf2<<<nblk_rows8, T>>>(W2, b1);    // agg L1 + relu + @W2
    k_agg_xf3<<<nblk_rows8, T>>>(W3, b2);    // agg L2 + relu + dot W3
    k_agg1_final<<<nblk_nodes, T>>>(b3, out);
}

// round 9
// speedup vs baseline: 3.1692x; 1.0393x over previous
#include <cuda_runtime.h>
#include <cuda_fp16.h>
#include <math.h>

#define N_NODES 150000
#define N_EDGES 2400000
#define F_IN 128
#define HID 32
#define SCAN_BS 256
#define SCAN_NB ((N_NODES + SCAN_BS - 1) / SCAN_BS)   // 586

#define EDGE_BLKS 2344        // 600000 edge-quads / 256 (rounded up)
#define X1_BLKS 2344          // ceil(150000/64) rows, 64 rows/block
#define HIST_BLKS 1172        // 8 edges/thread

// Scratch (allocation-free rule: __device__ globals)
__device__ float  g_dinv[N_NODES];
__device__ __half g_tmp[(size_t)N_NODES * HID];    // fp16 messages (9.6 MB)
__device__ __half g_acc[(size_t)N_NODES * HID];
__device__ float  g_tmp3[N_NODES];
__device__ int    g_cnt[N_NODES];
__device__ int    g_rowptr[N_NODES + 1];
__device__ int    g_cursor[N_NODES];
__device__ int    g_bsum[1024];
__device__ int    g_csr_src[N_EDGES];

// ---------------- hist: 8 edges per thread ----------------
__global__ __launch_bounds__(256) void k_hist(const int* __restrict__ dst) {
    int t = blockIdx.x * blockDim.x + threadIdx.x;
    int q0 = t * 2;
    if (q0 < N_EDGES / 4) {
        int4 d = __ldg((const int4*)dst + q0);
        atomicAdd(&g_cnt[d.x], 1);
        atomicAdd(&g_cnt[d.y], 1);
        atomicAdd(&g_cnt[d.z], 1);
        atomicAdd(&g_cnt[d.w], 1);
    }
    if (q0 + 1 < N_EDGES / 4) {
        int4 d = __ldg((const int4*)dst + q0 + 1);
        atomicAdd(&g_cnt[d.x], 1);
        atomicAdd(&g_cnt[d.y], 1);
        atomicAdd(&g_cnt[d.z], 1);
        atomicAdd(&g_cnt[d.w], 1);
    }
}

// ---------------- scan A ----------------
__global__ void k_scan_a() {
    __shared__ int wsum[8];
    int tid = threadIdx.x;
    int lane = tid & 31, w = tid >> 5;
    int i = blockIdx.x * SCAN_BS + tid;
    int v = (i < N_NODES) ? g_cnt[i] : 0;
    int s = v;
#pragma unroll
    for (int o = 1; o < 32; o <<= 1) {
        int t = __shfl_up_sync(0xffffffffu, s, o);
        if (lane >= o) s += t;
    }
    if (lane == 31) wsum[w] = s;
    __syncthreads();
    if (w == 0 && lane < 8) {
        int ws = wsum[lane];
#pragma unroll
        for (int o = 1; o < 8; o <<= 1) {
            int t = __shfl_up_sync(0xffu, ws, o);
            if (lane >= o) ws += t;
        }
        wsum[lane] = ws;
    }
    __syncthreads();
    int incl = s + (w > 0 ? wsum[w - 1] : 0);
    if (i < N_NODES) g_rowptr[i] = incl - v;
    if (tid == SCAN_BS - 1) g_bsum[blockIdx.x] = incl;
}

// ---------------- scan C (fused B): each block sums bsum[0..blk) itself ----------------
__global__ void k_scan_c() {
    __shared__ int red[8];
    __shared__ int s_off;
    int tid = threadIdx.x;
    int lane = tid & 31, w = tid >> 5;
    int blk = blockIdx.x;
    int p = 0;
    for (int j = tid; j < blk; j += 256) p += g_bsum[j];
#pragma unroll
    for (int o = 16; o > 0; o >>= 1) p += __shfl_down_sync(0xffffffffu, p, o);
    if (lane == 0) red[w] = p;
    __syncthreads();
    if (tid == 0) {
        int t = 0;
#pragma unroll
        for (int k = 0; k < 8; k++) t += red[k];
        s_off = t;
    }
    __syncthreads();
    int off = s_off;
    int i = blk * 256 + tid;
    if (i < N_NODES) {
        int r = g_rowptr[i] + off;
        g_rowptr[i] = r;
        g_cursor[i] = r;
        g_dinv[i] = rsqrtf((float)(g_cnt[i] + 1));  // +1 self loop
    }
    if (i == 0) g_rowptr[N_NODES] = N_EDGES;
}

// ---------------- xform1 body: 64 rows/block, 8 rows/thread, dinv-scaled inline ----------------
__device__ __forceinline__ void xform1_body8(
    const float* __restrict__ x, const float* __restrict__ W1,
    float* sW, float* sx, int row0)
{
    int tid = threadIdx.x;
    {
        const float4* Wv = (const float4*)W1;
        float4* sWv = (float4*)sW;
#pragma unroll
        for (int i = 0; i < 4; i++) sWv[tid + i * 256] = Wv[tid + i * 256];
    }
    if (row0 + 64 <= N_NODES) {
        const float4* xv = (const float4*)(x + (size_t)row0 * F_IN);
        float4* sxv = (float4*)sx;
#pragma unroll
        for (int i = 0; i < 8; i++) sxv[tid + i * 256] = xv[tid + i * 256];
    } else {
        for (int i = tid; i < 64 * F_IN; i += 256) {
            int r = i >> 7;
            sx[i] = (row0 + r < N_NODES) ? x[(size_t)(row0 + r) * F_IN + (i & 127)] : 0.0f;
        }
    }
    __syncthreads();

    int w = tid >> 5, f = tid & 31;
    float acc[8] = {0, 0, 0, 0, 0, 0, 0, 0};
    const float* xr = &sx[(w * 8) * F_IN];
#pragma unroll
    for (int k4 = 0; k4 < F_IN; k4 += 4) {
        float w0 = sW[(k4 + 0) * HID + f];
        float w1 = sW[(k4 + 1) * HID + f];
        float w2 = sW[(k4 + 2) * HID + f];
        float w3 = sW[(k4 + 3) * HID + f];
#pragma unroll
        for (int r = 0; r < 8; r++) {
            float4 xa = *(const float4*)(xr + r * F_IN + k4);
            acc[r] = fmaf(xa.x, w0, fmaf(xa.y, w1, fmaf(xa.z, w2, fmaf(xa.w, w3, acc[r]))));
        }
    }
#pragma unroll
    for (int r = 0; r < 8; r++) {
        int row = row0 + w * 8 + r;
        if (row < N_NODES)
            g_tmp[(size_t)row * HID + f] = __float2half_rn(g_dinv[row] * acc[r]);
    }
}

// ---------------- F2: interleaved fill (even) + xform1 scaled (odd) ----------------
__global__ __launch_bounds__(256) void k_F2(const int* __restrict__ src,
                                            const int* __restrict__ dst,
                                            const float* __restrict__ x,
                                            const float* __restrict__ W1) {
    __shared__ __align__(16) float sW[F_IN * HID];   // 16 KB
    __shared__ __align__(16) float sx[64 * F_IN];    // 32 KB
    int half_idx = blockIdx.x >> 1;
    if ((blockIdx.x & 1) == 0) {
        int t = half_idx * 256 + threadIdx.x;
        if (t < N_EDGES / 4) {
            int4 s = __ldg((const int4*)src + t);
            int4 d = __ldg((const int4*)dst + t);
            g_csr_src[atomicAdd(&g_cursor[d.x], 1)] = s.x;
            g_csr_src[atomicAdd(&g_cursor[d.y], 1)] = s.y;
            g_csr_src[atomicAdd(&g_cursor[d.z], 1)] = s.z;
            g_csr_src[atomicAdd(&g_cursor[d.w], 1)] = s.w;
        }
    } else {
        xform1_body8(x, W1, sW, sx, half_idx * 64);
    }
}

// ---------------- fused: agg(L1) + relu + @W2 + scale -> g_acc (fp16) ----------------
// 4 edges per lane-group: lane = eidx*8 + fg; 8-edge unrolled main loop for MLP.
__global__ void k_agg_xf2(const float* __restrict__ W2, const float* __restrict__ b1) {
    __shared__ float sW[HID * HID];
    __shared__ float sy[8][HID];
    int tid = threadIdx.x;  // 256
    for (int i = tid; i < HID * HID; i += 256) sW[i] = W2[i];
    __syncthreads();
    int w = tid >> 5, lane = tid & 31;
    int n = blockIdx.x * 8 + w;
    if (n >= N_NODES) return;  // warp-uniform
    int eidx = lane >> 3, fg = lane & 7;
    int e = g_rowptr[n];
    int e1 = g_rowptr[n + 1];
    float ax = 0.f, ay = 0.f, az = 0.f, aw = 0.f;
    for (; e + 8 <= e1; e += 8) {
        int s0 = g_csr_src[e + eidx];
        int s1 = g_csr_src[e + 4 + eidx];
        int2 v0 = *(const int2*)(g_tmp + (size_t)s0 * HID + fg * 4);
        int2 v1 = *(const int2*)(g_tmp + (size_t)s1 * HID + fg * 4);
        float2 a0 = __half22float2(*(__half2*)&v0.x);
        float2 b0 = __half22float2(*(__half2*)&v0.y);
        float2 a1 = __half22float2(*(__half2*)&v1.x);
        float2 b1f = __half22float2(*(__half2*)&v1.y);
        ax += a0.x + a1.x; ay += a0.y + a1.y;
        az += b0.x + b1f.x; aw += b0.y + b1f.y;
    }
    if (e + 4 <= e1) {
        int s = g_csr_src[e + eidx];
        int2 v = *(const int2*)(g_tmp + (size_t)s * HID + fg * 4);
        float2 f0 = __half22float2(*(__half2*)&v.x);
        float2 f1 = __half22float2(*(__half2*)&v.y);
        ax += f0.x; ay += f0.y; az += f1.x; aw += f1.y;
        e += 4;
    }
    if (eidx < e1 - e) {
        int s = g_csr_src[e + eidx];
        int2 v = *(const int2*)(g_tmp + (size_t)s * HID + fg * 4);
        float2 f0 = __half22float2(*(__half2*)&v.x);
        float2 f1 = __half22float2(*(__half2*)&v.y);
        ax += f0.x; ay += f0.y; az += f1.x; aw += f1.y;
    }
#pragma unroll
    for (int o = 8; o <= 16; o <<= 1) {
        ax += __shfl_xor_sync(0xffffffffu, ax, o);
        ay += __shfl_xor_sync(0xffffffffu, ay, o);
        az += __shfl_xor_sync(0xffffffffu, az, o);
        aw += __shfl_xor_sync(0xffffffffu, aw, o);
    }
    // self loop
    {
        int2 v = *(const int2*)(g_tmp + (size_t)n * HID + fg * 4);
        float2 f0 = __half22float2(*(__half2*)&v.x);
        float2 f1 = __half22float2(*(__half2*)&v.y);
        ax += f0.x; ay += f0.y; az += f1.x; aw += f1.y;
    }
    float di = g_dinv[n];
    float4 bv = *(const float4*)(b1 + fg * 4);
    float4 y;
    y.x = fmaxf(fmaf(di, ax, bv.x), 0.0f);
    y.y = fmaxf(fmaf(di, ay, bv.y), 0.0f);
    y.z = fmaxf(fmaf(di, az, bv.z), 0.0f);
    y.w = fmaxf(fmaf(di, aw, bv.w), 0.0f);
    if (eidx == 0) *(float4*)&sy[w][fg * 4] = y;
    __syncwarp();
    float t = 0.0f;
#pragma unroll
    for (int k = 0; k < HID; k++) t = fmaf(sy[w][k], sW[k * HID + lane], t);
    g_acc[(size_t)n * HID + lane] = __float2half_rn(di * t);
}

// ---------------- fused: agg(L2) + relu + dot W3 + scale -> g_tmp3 ----------------
__global__ void k_agg_xf3(const float* __restrict__ W3, const float* __restrict__ b2) {
    int tid = threadIdx.x;
    int w = tid >> 5, lane = tid & 31;
    int n = blockIdx.x * 8 + w;
    if (n >= N_NODES) return;  // warp-uniform
    int eidx = lane >> 3, fg = lane & 7;
    int e = g_rowptr[n];
    int e1 = g_rowptr[n + 1];
    float ax = 0.f, ay = 0.f, az = 0.f, aw = 0.f;
    for (; e + 8 <= e1; e += 8) {
        int s0 = g_csr_src[e + eidx];
        int s1 = g_csr_src[e + 4 + eidx];
        int2 v0 = *(const int2*)(g_acc + (size_t)s0 * HID + fg * 4);
        int2 v1 = *(const int2*)(g_acc + (size_t)s1 * HID + fg * 4);
        float2 a0 = __half22float2(*(__half2*)&v0.x);
        float2 b0 = __half22float2(*(__half2*)&v0.y);
        float2 a1 = __half22float2(*(__half2*)&v1.x);
        float2 b1f = __half22float2(*(__half2*)&v1.y);
        ax += a0.x + a1.x; ay += a0.y + a1.y;
        az += b0.x + b1f.x; aw += b0.y + b1f.y;
    }
    if (e + 4 <= e1) {
        int s = g_csr_src[e + eidx];
        int2 v = *(const int2*)(g_acc + (size_t)s * HID + fg * 4);
        float2 f0 = __half22float2(*(__half2*)&v.x);
        float2 f1 = __half22float2(*(__half2*)&v.y);
        ax += f0.x; ay += f0.y; az += f1.x; aw += f1.y;
        e += 4;
    }
    if (eidx < e1 - e) {
        int s = g_csr_src[e + eidx];
        int2 v = *(const int2*)(g_acc + (size_t)s * HID + fg * 4);
        float2 f0 = __half22float2(*(__half2*)&v.x);
        float2 f1 = __half22float2(*(__half2*)&v.y);
        ax += f0.x; ay += f0.y; az += f1.x; aw += f1.y;
    }
#pragma unroll
    for (int o = 8; o <= 16; o <<= 1) {
        ax += __shfl_xor_sync(0xffffffffu, ax, o);
        ay += __shfl_xor_sync(0xffffffffu, ay, o);
        az += __shfl_xor_sync(0xffffffffu, az, o);
        aw += __shfl_xor_sync(0xffffffffu, aw, o);
    }
    {
        int2 v = *(const int2*)(g_acc + (size_t)n * HID + fg * 4);
        float2 f0 = __half22float2(*(__half2*)&v.x);
        float2 f1 = __half22float2(*(__half2*)&v.y);
        ax += f0.x; ay += f0.y; az += f1.x; aw += f1.y;
    }
    float di = g_dinv[n];
    float4 bv = *(const float4*)(b2 + fg * 4);
    float4 wv = *(const float4*)(W3 + fg * 4);
    float t = fmaxf(fmaf(di, ax, bv.x), 0.0f) * wv.x
            + fmaxf(fmaf(di, ay, bv.y), 0.0f) * wv.y
            + fmaxf(fmaf(di, az, bv.z), 0.0f) * wv.z
            + fmaxf(fmaf(di, aw, bv.w), 0.0f) * wv.w;
#pragma unroll
    for (int o = 1; o <= 4; o <<= 1) t += __shfl_xor_sync(0xffffffffu, t, o);
    if (lane == 0) g_tmp3[n] = di * t;
}

// ---------------- scalar gather + final sigmoid ----------------
__global__ void k_agg1_final(const float* __restrict__ b3, float* __restrict__ out) {
    int n = blockIdx.x * blockDim.x + threadIdx.x;
    if (n >= N_NODES) return;
    int e = g_rowptr[n];
    int e1 = g_rowptr[n + 1];
    float a = g_tmp3[n];  // self loop
    for (; e + 4 <= e1; e += 4) {
        float v0 = g_tmp3[g_csr_src[e + 0]];
        float v1 = g_tmp3[g_csr_src[e + 1]];
        float v2 = g_tmp3[g_csr_src[e + 2]];
        float v3 = g_tmp3[g_csr_src[e + 3]];
        a += (v0 + v1) + (v2 + v3);
    }
    for (; e < e1; e++) a += g_tmp3[g_csr_src[e]];
    float z = fmaf(g_dinv[n], a, b3[0]);
    out[n] = 1.0f / (1.0f + __expf(-z));
}

extern "C" void kernel_launch(void* const* d_in, const int* in_sizes, int n_in,
                              void* d_out, int out_size) {
    // Resolve inputs by element count — robust to metadata ordering.
    int ix = -1, ie = -1, iw1 = -1, iw2 = -1, ib3 = -1;
    int i32[3], n32 = 0;
    for (int i = 0; i < n_in; i++) {
        switch (in_sizes[i]) {
            case 19200000: ix = i; break;
            case 4800000:  ie = i; break;
            case 4096:     iw1 = i; break;
            case 1024:     iw2 = i; break;
            case 1:        ib3 = i; break;
            case 32:       if (n32 < 3) i32[n32++] = i; break;
            default: break;
        }
    }
    int ib1, ib2, iw3;
    if (ie == 1) {  // dict order: x, edge_index, W1, b1, W2, b2, W3, b3
        ib1 = i32[0]; ib2 = i32[1]; iw3 = i32[2];
    } else {        // alphabetical: W1, W2, W3, b1, b2, b3, edge_index, x
        iw3 = i32[0]; ib1 = i32[1]; ib2 = i32[2];
    }

    const float* x  = (const float*)d_in[ix];
    const int* ei   = (const int*)d_in[ie];   // [2, E] int32
    const float* W1 = (const float*)d_in[iw1];
    const float* b1 = (const float*)d_in[ib1];
    const float* W2 = (const float*)d_in[iw2];
    const float* b2 = (const float*)d_in[ib2];
    const float* W3 = (const float*)d_in[iw3];
    const float* b3 = (const float*)d_in[ib3];
    float* out = (float*)d_out;

    const int* src = ei;
    const int* dst = ei + N_EDGES;

    const int T = 256;
    int nblk_nodes = (N_NODES + T - 1) / T;
    int nblk_rows8 = (N_NODES + 7) / 8;

    // zero counters via memset node (graph-capturable)
    void* cnt_ptr = nullptr;
    cudaGetSymbolAddress(&cnt_ptr, g_cnt);
    cudaMemsetAsync(cnt_ptr, 0, N_NODES * sizeof(int), 0);

    // CSR build: pure hist, scans (dinv+cursor ready)
    k_hist<<<HIST_BLKS, T>>>(dst);
    k_scan_a<<<SCAN_NB, SCAN_BS>>>();
    k_scan_c<<<SCAN_NB, SCAN_BS>>>();   // fused scan_b + scan_c
    // F2: interleaved fill + xform1 (dinv-scaled inline) — no scale pass needed
    k_F2<<<EDGE_BLKS + X1_BLKS, T>>>(src, dst, x, W1);

    k_agg_xf2<<<nblk_rows8, T>>>(W2, b1);    // agg L1 + relu + @W2
    k_agg_xf3<<<nblk_rows8, T>>>(W3, b2);    // agg L2 + relu + dot W3
    k_agg1_final<<<nblk_nodes, T>>>(b3, out);
}